// round 9
// baseline (speedup 1.0000x reference)
#include <cuda_runtime.h>
#include <cuda_bf16.h>
#include <cstdint>

#define Bq 8
#define Nq 1024
#define Cq 768
#define Hq 12
#define HDq 64
#define Rq 16
#define ROWS (Bq*Nq)
#define SCALE 0.125f
#define QSCALE 0.18033688011112042f   // 0.125 * log2(e)

typedef __nv_bfloat16 bf16;

// ---------------- mma.sync / ldmatrix / cp.async helpers ----------------
__device__ __forceinline__ uint32_t smem_u32(const void* p) {
    uint32_t a;
    asm("{ .reg .u64 t; cvta.to.shared.u64 t, %1; cvt.u32.u64 %0, t; }" : "=r"(a) : "l"(p));
    return a;
}
__device__ __forceinline__ void ldsm4(uint32_t& r0, uint32_t& r1, uint32_t& r2, uint32_t& r3,
                                      uint32_t addr) {
    asm volatile("ldmatrix.sync.aligned.m8n8.x4.shared.b16 {%0,%1,%2,%3}, [%4];"
                 : "=r"(r0), "=r"(r1), "=r"(r2), "=r"(r3) : "r"(addr));
}
__device__ __forceinline__ void ldsm4t(uint32_t& r0, uint32_t& r1, uint32_t& r2, uint32_t& r3,
                                       uint32_t addr) {
    asm volatile("ldmatrix.sync.aligned.m8n8.x4.trans.shared.b16 {%0,%1,%2,%3}, [%4];"
                 : "=r"(r0), "=r"(r1), "=r"(r2), "=r"(r3) : "r"(addr));
}
__device__ __forceinline__ void mma_bf16(float* c, uint32_t a0, uint32_t a1, uint32_t a2,
                                         uint32_t a3, uint32_t b0, uint32_t b1) {
    asm("mma.sync.aligned.m16n8k16.row.col.f32.bf16.bf16.f32 "
        "{%0,%1,%2,%3}, {%4,%5,%6,%7}, {%8,%9}, {%0,%1,%2,%3};"
        : "+f"(c[0]), "+f"(c[1]), "+f"(c[2]), "+f"(c[3])
        : "r"(a0), "r"(a1), "r"(a2), "r"(a3), "r"(b0), "r"(b1));
}
__device__ __forceinline__ void cp16(uint32_t dst, const void* src) {
    asm volatile("cp.async.cg.shared.global [%0], [%1], 16;" :: "r"(dst), "l"(src));
}
__device__ __forceinline__ void cp_commit() {
    asm volatile("cp.async.commit_group;" ::: "memory");
}
template <int N>
__device__ __forceinline__ void cp_wait() {
    asm volatile("cp.async.wait_group %0;" :: "n"(N) : "memory");
}
__device__ __forceinline__ float ex2(float x) {
    float y; asm("ex2.approx.f32 %0, %1;" : "=f"(y) : "f"(x)); return y;
}

__device__ __forceinline__ void split_bf16(float v, bf16& h, bf16& l) {
    h = __float2bfloat16(v);
    l = __float2bfloat16(v - __bfloat162float(h));
}
__device__ __forceinline__ uint32_t pkbf(bf16 a, bf16 b) {
    __nv_bfloat162 t; t.x = a; t.y = b;
    return *(uint32_t*)&t;
}

// ---------------- scratch ----------------
__device__ bf16 g_qh[Bq*Hq*Nq*HDq], g_ql[Bq*Hq*Nq*HDq];
__device__ bf16 g_kh[Bq*Hq*Nq*HDq], g_kl[Bq*Hq*Nq*HDq];
__device__ bf16 g_vh[Bq*Hq*Nq*HDq], g_vl[Bq*Hq*Nq*HDq];
__device__ bf16 g_Xh[ROWS*Cq], g_Xl[ROWS*Cq];
__device__ bf16 g_Wth[3][Cq*Cq], g_Wtl[3][Cq*Cq];     // (W + bw*la@lb)^T hi/lo
__device__ bf16 g_Wpth[Cq*Cq], g_Wptl[Cq*Cq];
__device__ bf16 g_atth[ROWS*Cq], g_attl[ROWS*Cq];

// ---------------- prep kernels ----------------
__global__ void convert_x_kernel(const float* __restrict__ X) {
    int i = blockIdx.x * blockDim.x + threadIdx.x;
    if (i < ROWS * Cq) {
        bf16 h, l; split_bf16(X[i], h, l);
        g_Xh[i] = h; g_Xl[i] = l;
    }
}

// W' = W + bw*(la@lb)  (sel<3), or plain Wp (sel=3); write transposed hi/lo
__global__ __launch_bounds__(256) void wprime_kernel(
        const float* __restrict__ Wq_, const float* __restrict__ Wk_,
        const float* __restrict__ Wv_, const float* __restrict__ Wp_,
        const float* __restrict__ laq, const float* __restrict__ lbq,
        const float* __restrict__ lak, const float* __restrict__ lbk,
        const float* __restrict__ lav, const float* __restrict__ lbv,
        const float* __restrict__ bw) {
    __shared__ float ws[32][33];
    __shared__ float las[32][16];
    __shared__ float lbs[16][33];
    int sel = blockIdx.z;
    const float* W  = (sel == 0) ? Wq_ : (sel == 1) ? Wk_ : (sel == 2) ? Wv_ : Wp_;
    const float* la = (sel == 0) ? laq : (sel == 1) ? lak : lav;
    const float* lb = (sel == 0) ? lbq : (sel == 1) ? lbk : lbv;
    bf16* dh = (sel < 3) ? g_Wth[sel] : g_Wpth;
    bf16* dl = (sel < 3) ? g_Wtl[sel] : g_Wptl;
    int tid = threadIdx.x, tx = tid & 31, ty = tid >> 5;
    int kb = blockIdx.y * 32, nb = blockIdx.x * 32;
    #pragma unroll
    for (int s = 0; s < 4; s++)
        ws[ty + 8 * s][tx] = W[(size_t)(kb + ty + 8 * s) * Cq + nb + tx];
    if (sel < 3) {
        for (int l = tid; l < 512; l += 256) {
            las[l >> 4][l & 15] = la[(size_t)(kb + (l >> 4)) * Rq + (l & 15)];
            lbs[l >> 5][l & 31] = lb[(size_t)(l >> 5) * Cq + nb + (l & 31)];
        }
        __syncthreads();
        float w = bw[sel];
        #pragma unroll
        for (int s = 0; s < 4; s++) {
            int i = ty + 8 * s;
            float acc = 0.f;
            #pragma unroll
            for (int r = 0; r < Rq; r++) acc = fmaf(las[i][r], lbs[r][tx], acc);
            ws[i][tx] = fmaf(w, acc, ws[i][tx]);
        }
    }
    __syncthreads();
    #pragma unroll
    for (int s = 0; s < 4; s++) {
        float v = ws[tx][ty + 8 * s];
        bf16 h, l; split_bf16(v, h, l);
        size_t idx = (size_t)(nb + ty + 8 * s) * Cq + kb + tx;
        dh[idx] = h; dl[idx] = l;
    }
}

// ---------------- pipelined bf16 GEMM core (double-buffer, 2 CTAs/SM) ----------------
#define PITCH 40
#define NSTAGE 2
#define TILE_B 10240
#define STAGE_B (4*TILE_B)
#define GEMM_DSMEM (NSTAGE*STAGE_B)        // 80KB -> 2 CTAs/SM

__device__ __forceinline__ void issue_chunk(uint32_t sbase, int stage,
                                            const bf16* ah, const bf16* al,
                                            const bf16* bh, const bf16* bl,
                                            int stride, int tid) {
    uint32_t st = sbase + stage * STAGE_B;
    const bf16* srcs[4] = {ah, al, bh, bl};
    #pragma unroll
    for (int t = 0; t < 4; t++) {
        #pragma unroll
        for (int i = 0; i < 2; i++) {
            int idx = tid + 256 * i;
            int row = idx >> 2, seg = idx & 3;
            cp16(st + t * TILE_B + (row * PITCH + seg * 8) * 2,
                 srcs[t] + (size_t)row * stride + seg * 8);
        }
    }
    cp_commit();
}

__device__ __forceinline__ void compute_chunk(uint32_t sbase, int stage,
                                              float C[2][8][4], int a_off, int b_off) {
    uint32_t st = sbase + stage * STAGE_B;
    uint32_t aH = st, aL = st + TILE_B, bH = st + 2 * TILE_B, bL = st + 3 * TILE_B;
    #pragma unroll
    for (int kt = 0; kt < 2; kt++) {
        int ko = kt * 16;
        uint32_t ah[2][4], al[2][4], bh[8][2], bl[8][2];
        #pragma unroll
        for (int mt = 0; mt < 2; mt++) {
            int off = (a_off + mt * 16 * PITCH + ko) * 2;
            ldsm4(ah[mt][0], ah[mt][1], ah[mt][2], ah[mt][3], aH + off);
            ldsm4(al[mt][0], al[mt][1], al[mt][2], al[mt][3], aL + off);
        }
        #pragma unroll
        for (int p = 0; p < 4; p++) {
            int off = (b_off + p * 16 * PITCH + ko) * 2;
            ldsm4(bh[2*p][0], bh[2*p][1], bh[2*p+1][0], bh[2*p+1][1], bH + off);
            ldsm4(bl[2*p][0], bl[2*p][1], bl[2*p+1][0], bl[2*p+1][1], bL + off);
        }
        #pragma unroll
        for (int mt = 0; mt < 2; mt++)
            #pragma unroll
            for (int nt = 0; nt < 8; nt++) {
                mma_bf16(C[mt][nt], ah[mt][0], ah[mt][1], ah[mt][2], ah[mt][3],
                         bh[nt][0], bh[nt][1]);
                mma_bf16(C[mt][nt], ah[mt][0], ah[mt][1], ah[mt][2], ah[mt][3],
                         bl[nt][0], bl[nt][1]);
                mma_bf16(C[mt][nt], al[mt][0], al[mt][1], al[mt][2], al[mt][3],
                         bh[nt][0], bh[nt][1]);
            }
    }
}

// ---------------- qkv GEMM (LoRA folded into W') -> bf16 hi/lo head-split ----------------
__global__ __launch_bounds__(256, 2) void gemm_qkv_kernel() {
    extern __shared__ char dsm[];
    uint32_t sbase = smem_u32(dsm);
    int tid = threadIdx.x, lid = tid & 31, wid = tid >> 5;
    int wm = (wid & 3) * 32, wn = (wid >> 2) * 64;
    int type = blockIdx.z;
    int rowBase = blockIdx.y * 128, colBase = blockIdx.x * 128;

    const bf16* Xh = g_Xh + (size_t)rowBase * Cq;
    const bf16* Xl = g_Xl + (size_t)rowBase * Cq;
    const bf16* Wh = g_Wth[type] + (size_t)colBase * Cq;
    const bf16* Wl = g_Wtl[type] + (size_t)colBase * Cq;

    float C[2][8][4];
    #pragma unroll
    for (int i = 0; i < 2; i++)
        #pragma unroll
        for (int j = 0; j < 8; j++)
            #pragma unroll
            for (int k = 0; k < 4; k++) C[i][j][k] = 0.f;

    int a_off = (wm + (lid & 15)) * PITCH + ((lid >> 4) & 1) * 8;
    int b_off = (wn + ((lid >> 4) & 1) * 8 + (lid & 7)) * PITCH + ((lid >> 3) & 1) * 8;

    const int NCH = 24;
    issue_chunk(sbase, 0, Xh, Xl, Wh, Wl, Cq, tid);
    for (int c = 0; c < NCH; c++) {
        cp_wait<0>();
        __syncthreads();
        int nc = c + 1;
        if (nc < NCH)
            issue_chunk(sbase, nc & 1, Xh + nc * 32, Xl + nc * 32,
                        Wh + nc * 32, Wl + nc * 32, Cq, tid);
        compute_chunk(sbase, c & 1, C, a_off, b_off);
    }

    bf16* outh = (type == 0) ? g_qh : (type == 1) ? g_kh : g_vh;
    bf16* outl = (type == 0) ? g_ql : (type == 1) ? g_kl : g_vl;
    float scl = (type == 0) ? QSCALE : 1.f;   // fold 1/sqrt(HD) * log2(e) into q
    #pragma unroll
    for (int mt = 0; mt < 2; mt++)
        #pragma unroll
        for (int nt = 0; nt < 8; nt++) {
            int col = colBase + wn + nt * 8 + (lid & 3) * 2;
            int h = col >> 6, hd = col & 63;
            #pragma unroll
            for (int half = 0; half < 2; half++) {
                int row = rowBase + wm + mt * 16 + (lid >> 2) + half * 8;
                int b_ = row >> 10, n = row & 1023;
                float v0 = C[mt][nt][half * 2] * scl, v1 = C[mt][nt][half * 2 + 1] * scl;
                bf16 h0, l0, h1, l1;
                split_bf16(v0, h0, l0); split_bf16(v1, h1, l1);
                size_t base = (((size_t)(b_ * Hq + h) * Nq) + n) * HDq + hd;
                *(uint32_t*)&outh[base] = pkbf(h0, h1);
                *(uint32_t*)&outl[base] = pkbf(l0, l1);
            }
        }
}

// ---------------- output projection GEMM + bias ----------------
__global__ __launch_bounds__(256, 2) void gemm_out_kernel(const float* __restrict__ bias,
                                                          float* __restrict__ out) {
    extern __shared__ char dsm[];
    uint32_t sbase = smem_u32(dsm);
    int tid = threadIdx.x, lid = tid & 31, wid = tid >> 5;
    int wm = (wid & 3) * 32, wn = (wid >> 2) * 64;
    int rowBase = blockIdx.y * 128, colBase = blockIdx.x * 128;

    const bf16* Ah = g_atth + (size_t)rowBase * Cq;
    const bf16* Al = g_attl + (size_t)rowBase * Cq;
    const bf16* Wh = g_Wpth + (size_t)colBase * Cq;
    const bf16* Wl = g_Wptl + (size_t)colBase * Cq;

    float C[2][8][4];
    #pragma unroll
    for (int i = 0; i < 2; i++)
        #pragma unroll
        for (int j = 0; j < 8; j++)
            #pragma unroll
            for (int k = 0; k < 4; k++) C[i][j][k] = 0.f;

    int a_off = (wm + (lid & 15)) * PITCH + ((lid >> 4) & 1) * 8;
    int b_off = (wn + ((lid >> 4) & 1) * 8 + (lid & 7)) * PITCH + ((lid >> 3) & 1) * 8;

    const int NCH = 24;
    issue_chunk(sbase, 0, Ah, Al, Wh, Wl, Cq, tid);
    for (int c = 0; c < NCH; c++) {
        cp_wait<0>();
        __syncthreads();
        int nc = c + 1;
        if (nc < NCH)
            issue_chunk(sbase, nc & 1, Ah + nc * 32, Al + nc * 32,
                        Wh + nc * 32, Wl + nc * 32, Cq, tid);
        compute_chunk(sbase, c & 1, C, a_off, b_off);
    }

    #pragma unroll
    for (int mt = 0; mt < 2; mt++)
        #pragma unroll
        for (int nt = 0; nt < 8; nt++) {
            int col = colBase + wn + nt * 8 + (lid & 3) * 2;
            float2 bv = *(const float2*)&bias[col];
            #pragma unroll
            for (int half = 0; half < 2; half++) {
                int row = rowBase + wm + mt * 16 + (lid >> 2) + half * 8;
                float2 v = make_float2(C[mt][nt][half * 2] + bv.x, C[mt][nt][half * 2 + 1] + bv.y);
                *(float2*)&out[(size_t)row * Cq + col] = v;
            }
        }
}

// ---------------- FA2-style mma attention: warp = 16 rows, register softmax ----------------
#define KVP 72
#define QBYTES 18432                 // 128*72*2
#define KVTILE 9216                  // 64*72*2
#define KVBUF (4*KVTILE)             // Kh,Kl,Vh,Vl
#define AOFF_KV (2*QBYTES)
#define ATTN_SMEM (2*QBYTES + 2*KVBUF)   // 110592

__global__ __launch_bounds__(256, 2) void attn_kernel() {
    extern __shared__ char smx[];
    uint32_t sb = smem_u32(smx);
    int tid = threadIdx.x, lid = tid & 31, wid = tid >> 5;
    int wm = wid * 16;
    int qt = blockIdx.x, head = blockIdx.y, b = blockIdx.z;
    size_t bh = (size_t)(b * Hq + head) * Nq * HDq;
    const bf16* Qhg = g_qh + bh + (size_t)qt * 128 * HDq;
    const bf16* Qlg = g_ql + bh + (size_t)qt * 128 * HDq;

    // prologue: Q (hi+lo) and KV tile 0
    #pragma unroll
    for (int i = 0; i < 4; i++) {
        int idx = tid + 256 * i;
        int row = idx >> 3, seg = idx & 7;
        cp16(sb + (row * KVP + seg * 8) * 2, Qhg + row * HDq + seg * 8);
        cp16(sb + QBYTES + (row * KVP + seg * 8) * 2, Qlg + row * HDq + seg * 8);
    }
    {
        const bf16* srcs[4] = {g_kh + bh, g_kl + bh, g_vh + bh, g_vl + bh};
        #pragma unroll
        for (int t = 0; t < 4; t++)
            #pragma unroll
            for (int i = 0; i < 2; i++) {
                int idx = tid + 256 * i;
                int row = idx >> 3, seg = idx & 7;
                cp16(sb + AOFF_KV + t * KVTILE + (row * KVP + seg * 8) * 2,
                     srcs[t] + row * HDq + seg * 8);
            }
    }
    cp_commit();

    // running softmax state: per-thread partial l (deferred reduction)
    float mA = -1e30f, mB = -1e30f, lA = 0.f, lB = 0.f;
    float co[8][4];
    #pragma unroll
    for (int j = 0; j < 8; j++)
        #pragma unroll
        for (int k = 0; k < 4; k++) co[j][k] = 0.f;

    for (int it = 0; it < 16; it++) {
        cp_wait<0>();
        __syncthreads();
        if (it + 1 < 16) {
            uint32_t dst = sb + AOFF_KV + ((it + 1) & 1) * KVBUF;
            const bf16* srcs[4] = {g_kh + bh + (size_t)(it + 1) * 64 * HDq,
                                   g_kl + bh + (size_t)(it + 1) * 64 * HDq,
                                   g_vh + bh + (size_t)(it + 1) * 64 * HDq,
                                   g_vl + bh + (size_t)(it + 1) * 64 * HDq};
            #pragma unroll
            for (int t = 0; t < 4; t++)
                #pragma unroll
                for (int i = 0; i < 2; i++) {
                    int idx = tid + 256 * i;
                    int row = idx >> 3, seg = idx & 7;
                    cp16(dst + t * KVTILE + (row * KVP + seg * 8) * 2,
                         srcs[t] + row * HDq + seg * 8);
                }
            cp_commit();
        }

        uint32_t kv = sb + AOFF_KV + (it & 1) * KVBUF;
        uint32_t aKh = kv, aKl = kv + KVTILE, aVh = kv + 2 * KVTILE, aVl = kv + 3 * KVTILE;

        // ---- S = Q K^T : m16 x n64 per warp, 3-pass (logits in log2 domain) ----
        float cs[8][4];
        #pragma unroll
        for (int j = 0; j < 8; j++)
            #pragma unroll
            for (int k = 0; k < 4; k++) cs[j][k] = 0.f;

        #pragma unroll
        for (int ks = 0; ks < 4; ks++) {
            int ko = ks * 16;
            uint32_t qh[4], ql[4], kh[8][2], kl[8][2];
            int offq = ((wm + (lid & 15)) * KVP + ((lid >> 4) & 1) * 8 + ko) * 2;
            ldsm4(qh[0], qh[1], qh[2], qh[3], sb + offq);
            ldsm4(ql[0], ql[1], ql[2], ql[3], sb + QBYTES + offq);
            #pragma unroll
            for (int p = 0; p < 4; p++) {
                int offb = ((p * 16 + ((lid >> 4) & 1) * 8 + (lid & 7)) * KVP
                            + ((lid >> 3) & 1) * 8 + ko) * 2;
                ldsm4(kh[2*p][0], kh[2*p][1], kh[2*p+1][0], kh[2*p+1][1], aKh + offb);
                ldsm4(kl[2*p][0], kl[2*p][1], kl[2*p+1][0], kl[2*p+1][1], aKl + offb);
            }
            #pragma unroll
            for (int nt = 0; nt < 8; nt++) {
                mma_bf16(cs[nt], qh[0], qh[1], qh[2], qh[3], kh[nt][0], kh[nt][1]);
                mma_bf16(cs[nt], qh[0], qh[1], qh[2], qh[3], kl[nt][0], kl[nt][1]);
                mma_bf16(cs[nt], ql[0], ql[1], ql[2], ql[3], kh[nt][0], kh[nt][1]);
            }
        }

        // ---- register softmax: packed-bf16 max reduce (2 shfls), deferred l ----
        float mxA = -1e30f, mxB = -1e30f;
        #pragma unroll
        for (int nt = 0; nt < 8; nt++) {
            mxA = fmaxf(mxA, fmaxf(cs[nt][0], cs[nt][1]));
            mxB = fmaxf(mxB, fmaxf(cs[nt][2], cs[nt][3]));
        }
        uint32_t pk = pkbf(__float2bfloat16(mxA), __float2bfloat16(mxB));
        #pragma unroll
        for (int d = 1; d <= 2; d <<= 1) {
            uint32_t o = __shfl_xor_sync(0xffffffffu, pk, d);
            __nv_bfloat162 pa = *(__nv_bfloat162*)&pk, pb = *(__nv_bfloat162*)&o;
            float f0 = fmaxf(__bfloat162float(pa.x), __bfloat162float(pb.x));
            float f1 = fmaxf(__bfloat162float(pa.y), __bfloat162float(pb.y));
            pk = pkbf(__float2bfloat16(f0), __float2bfloat16(f1));
        }
        {
            __nv_bfloat162 mm = *(__nv_bfloat162*)&pk;
            mxA = __bfloat162float(mm.x); mxB = __bfloat162float(mm.y);
        }
        float mnA = fmaxf(mA, mxA), mnB = fmaxf(mB, mxB);
        float alA = ex2(mA - mnA), alB = ex2(mB - mnB);
        float psA = 0.f, psB = 0.f;
        #pragma unroll
        for (int nt = 0; nt < 8; nt++) {
            cs[nt][0] = ex2(cs[nt][0] - mnA);
            cs[nt][1] = ex2(cs[nt][1] - mnA);
            cs[nt][2] = ex2(cs[nt][2] - mnB);
            cs[nt][3] = ex2(cs[nt][3] - mnB);
            psA += cs[nt][0] + cs[nt][1];
            psB += cs[nt][2] + cs[nt][3];
        }
        lA = lA * alA + psA; mA = mnA;     // per-thread partial sums (exact: alpha row-uniform)
        lB = lB * alB + psB; mB = mnB;

        // ---- repack P c-frags -> a-frags (hi/lo) in registers ----
        uint32_t pah[4][4], pal[4][4];
        #pragma unroll
        for (int ks = 0; ks < 4; ks++) {
            #pragma unroll
            for (int half = 0; half < 2; half++) {
                int nt = 2 * ks + half;
                bf16 h0, l0, h1, l1, h2, l2, h3, l3;
                split_bf16(cs[nt][0], h0, l0); split_bf16(cs[nt][1], h1, l1);
                split_bf16(cs[nt][2], h2, l2); split_bf16(cs[nt][3], h3, l3);
                pah[ks][2 * half]     = pkbf(h0, h1);
                pah[ks][2 * half + 1] = pkbf(h2, h3);
                pal[ks][2 * half]     = pkbf(l0, l1);
                pal[ks][2 * half + 1] = pkbf(l2, l3);
            }
        }

        // ---- rescale O, O += P V (3-pass, V via ldmatrix.trans) ----
        #pragma unroll
        for (int nt = 0; nt < 8; nt++) {
            co[nt][0] *= alA; co[nt][1] *= alA;
            co[nt][2] *= alB; co[nt][3] *= alB;
        }
        #pragma unroll
        for (int ks = 0; ks < 4; ks++) {
            int ko = ks * 16;
            uint32_t vh[8][2], vl[8][2];
            #pragma unroll
            for (int dt = 0; dt < 4; dt++) {
                int offv = ((ko + (lid & 15)) * KVP + dt * 16 + ((lid >> 4) & 1) * 8) * 2;
                ldsm4t(vh[2*dt][0], vh[2*dt][1], vh[2*dt+1][0], vh[2*dt+1][1], aVh + offv);
                ldsm4t(vl[2*dt][0], vl[2*dt][1], vl[2*dt+1][0], vl[2*dt+1][1], aVl + offv);
            }
            #pragma unroll
            for (int nt = 0; nt < 8; nt++) {
                mma_bf16(co[nt], pah[ks][0], pah[ks][1], pah[ks][2], pah[ks][3],
                         vh[nt][0], vh[nt][1]);
                mma_bf16(co[nt], pah[ks][0], pah[ks][1], pah[ks][2], pah[ks][3],
                         vl[nt][0], vl[nt][1]);
                mma_bf16(co[nt], pal[ks][0], pal[ks][1], pal[ks][2], pal[ks][3],
                         vh[nt][0], vh[nt][1]);
            }
        }
    }

    // ---- final l reduction across the 4 lanes sharing each row ----
    lA += __shfl_xor_sync(0xffffffffu, lA, 1);
    lA += __shfl_xor_sync(0xffffffffu, lA, 2);
    lB += __shfl_xor_sync(0xffffffffu, lB, 1);
    lB += __shfl_xor_sync(0xffffffffu, lB, 2);

    // ---- epilogue: normalize, write bf16 hi/lo to g_att [B,N,C] ----
    float invA = 1.f / lA, invB = 1.f / lB;
    int rA = qt * 128 + wm + (lid >> 2);
    #pragma unroll
    for (int nt = 0; nt < 8; nt++) {
        int col = head * HDq + nt * 8 + (lid & 3) * 2;
        float v0 = co[nt][0] * invA, v1 = co[nt][1] * invA;
        float v2 = co[nt][2] * invB, v3 = co[nt][3] * invB;
        bf16 h0, l0, h1, l1;
        split_bf16(v0, h0, l0); split_bf16(v1, h1, l1);
        size_t base = (size_t)(b * Nq + rA) * Cq + col;
        *(uint32_t*)&g_atth[base] = pkbf(h0, h1);
        *(uint32_t*)&g_attl[base] = pkbf(l0, l1);
        split_bf16(v2, h0, l0); split_bf16(v3, h1, l1);
        size_t base2 = (size_t)(b * Nq + rA + 8) * Cq + col;
        *(uint32_t*)&g_atth[base2] = pkbf(h0, h1);
        *(uint32_t*)&g_attl[base2] = pkbf(l0, l1);
    }
}

extern "C" void kernel_launch(void* const* d_in, const int* in_sizes, int n_in,
                              void* d_out, int out_size) {
    const float* x    = (const float*)d_in[0];
    const float* Wq   = (const float*)d_in[1];
    const float* Wk   = (const float*)d_in[2];
    const float* Wv   = (const float*)d_in[3];
    const float* Wp   = (const float*)d_in[4];
    const float* bp   = (const float*)d_in[5];
    const float* la_q = (const float*)d_in[6];
    const float* lb_q = (const float*)d_in[7];
    const float* la_k = (const float*)d_in[8];
    const float* lb_k = (const float*)d_in[9];
    const float* la_v = (const float*)d_in[10];
    const float* lb_v = (const float*)d_in[11];
    const float* bw   = (const float*)d_in[12];
    float* out = (float*)d_out;

    convert_x_kernel<<<(ROWS * Cq + 255) / 256, 256>>>(x);
    wprime_kernel<<<dim3(24, 24, 4), 256>>>(Wq, Wk, Wv, Wp,
                                            la_q, lb_q, la_k, lb_k, la_v, lb_v, bw);

    cudaFuncSetAttribute(gemm_qkv_kernel, cudaFuncAttributeMaxDynamicSharedMemorySize, GEMM_DSMEM);
    gemm_qkv_kernel<<<dim3(6, 64, 3), 256, GEMM_DSMEM>>>();

    cudaFuncSetAttribute(attn_kernel, cudaFuncAttributeMaxDynamicSharedMemorySize, ATTN_SMEM);
    attn_kernel<<<dim3(Nq / 128, Hq, Bq), 256, ATTN_SMEM>>>();

    cudaFuncSetAttribute(gemm_out_kernel, cudaFuncAttributeMaxDynamicSharedMemorySize, GEMM_DSMEM);
    gemm_out_kernel<<<dim3(6, 64), 256, GEMM_DSMEM>>>(bp, out);
}

// round 11
// speedup vs baseline: 1.5467x; 1.5467x over previous
#include <cuda_runtime.h>
#include <cuda_fp16.h>
#include <cstdint>

#define Bq 8
#define Nq 1024
#define Cq 768
#define Hq 12
#define HDq 64
#define Rq 16
#define ROWS (Bq*Nq)
#define QSCALE 0.18033688011112042f   // 0.125 * log2(e)

typedef __half fp16;

// ---------------- helpers ----------------
__device__ __forceinline__ uint32_t smem_u32(const void* p) {
    uint32_t a;
    asm("{ .reg .u64 t; cvta.to.shared.u64 t, %1; cvt.u32.u64 %0, t; }" : "=r"(a) : "l"(p));
    return a;
}
__device__ __forceinline__ void ldsm4(uint32_t& r0, uint32_t& r1, uint32_t& r2, uint32_t& r3,
                                      uint32_t addr) {
    asm volatile("ldmatrix.sync.aligned.m8n8.x4.shared.b16 {%0,%1,%2,%3}, [%4];"
                 : "=r"(r0), "=r"(r1), "=r"(r2), "=r"(r3) : "r"(addr));
}
__device__ __forceinline__ void ldsm4t(uint32_t& r0, uint32_t& r1, uint32_t& r2, uint32_t& r3,
                                       uint32_t addr) {
    asm volatile("ldmatrix.sync.aligned.m8n8.x4.trans.shared.b16 {%0,%1,%2,%3}, [%4];"
                 : "=r"(r0), "=r"(r1), "=r"(r2), "=r"(r3) : "r"(addr));
}
__device__ __forceinline__ void mma_f16(float* c, uint32_t a0, uint32_t a1, uint32_t a2,
                                        uint32_t a3, uint32_t b0, uint32_t b1) {
    asm("mma.sync.aligned.m16n8k16.row.col.f32.f16.f16.f32 "
        "{%0,%1,%2,%3}, {%4,%5,%6,%7}, {%8,%9}, {%0,%1,%2,%3};"
        : "+f"(c[0]), "+f"(c[1]), "+f"(c[2]), "+f"(c[3])
        : "r"(a0), "r"(a1), "r"(a2), "r"(a3), "r"(b0), "r"(b1));
}
__device__ __forceinline__ void cp16(uint32_t dst, const void* src) {
    asm volatile("cp.async.cg.shared.global [%0], [%1], 16;" :: "r"(dst), "l"(src));
}
__device__ __forceinline__ void cp_commit() {
    asm volatile("cp.async.commit_group;" ::: "memory");
}
template <int N>
__device__ __forceinline__ void cp_wait() {
    asm volatile("cp.async.wait_group %0;" :: "n"(N) : "memory");
}
__device__ __forceinline__ float ex2(float x) {
    float y; asm("ex2.approx.f32 %0, %1;" : "=f"(y) : "f"(x)); return y;
}
__device__ __forceinline__ uint32_t pkh(float a, float b) {
    __half2 t = __floats2half2_rn(a, b);
    return *(uint32_t*)&t;
}
__device__ __forceinline__ void split_h(float v, fp16& h, fp16& l) {
    h = __float2half_rn(v);
    l = __float2half_rn(v - __half2float(h));
}

// ---------------- scratch ----------------
__device__ fp16 g_q[Bq*Hq*Nq*HDq];                    // single, pre-scaled
__device__ fp16 g_kh[Bq*Hq*Nq*HDq], g_kl[Bq*Hq*Nq*HDq];
__device__ fp16 g_v[Bq*Hq*Nq*HDq];                    // single
__device__ fp16 g_X16[ROWS*Cq];                       // single
__device__ fp16 g_Wth[3][Cq*Cq], g_Wtl[3][Cq*Cq];     // (W + bw*la@lb)^T hi/lo
__device__ fp16 g_Wpth[Cq*Cq], g_Wptl[Cq*Cq];
__device__ fp16 g_att[ROWS*Cq];                       // single

// ---------------- prep kernels ----------------
__global__ void convert_x_kernel(const float* __restrict__ X) {
    int i = blockIdx.x * blockDim.x + threadIdx.x;
    if (i < ROWS * Cq) g_X16[i] = __float2half_rn(X[i]);
}

// W' = W + bw*(la@lb)  (sel<3), or plain Wp (sel=3); write transposed hi/lo fp16
__global__ __launch_bounds__(256) void wprime_kernel(
        const float* __restrict__ Wq_, const float* __restrict__ Wk_,
        const float* __restrict__ Wv_, const float* __restrict__ Wp_,
        const float* __restrict__ laq, const float* __restrict__ lbq,
        const float* __restrict__ lak, const float* __restrict__ lbk,
        const float* __restrict__ lav, const float* __restrict__ lbv,
        const float* __restrict__ bw) {
    __shared__ float ws[32][33];
    __shared__ float las[32][16];
    __shared__ float lbs[16][33];
    int sel = blockIdx.z;
    const float* W  = (sel == 0) ? Wq_ : (sel == 1) ? Wk_ : (sel == 2) ? Wv_ : Wp_;
    const float* la = (sel == 0) ? laq : (sel == 1) ? lak : lav;
    const float* lb = (sel == 0) ? lbq : (sel == 1) ? lbk : lbv;
    fp16* dh = (sel < 3) ? g_Wth[sel] : g_Wpth;
    fp16* dl = (sel < 3) ? g_Wtl[sel] : g_Wptl;
    int tid = threadIdx.x, tx = tid & 31, ty = tid >> 5;
    int kb = blockIdx.y * 32, nb = blockIdx.x * 32;
    #pragma unroll
    for (int s = 0; s < 4; s++)
        ws[ty + 8 * s][tx] = W[(size_t)(kb + ty + 8 * s) * Cq + nb + tx];
    if (sel < 3) {
        for (int l = tid; l < 512; l += 256) {
            las[l >> 4][l & 15] = la[(size_t)(kb + (l >> 4)) * Rq + (l & 15)];
            lbs[l >> 5][l & 31] = lb[(size_t)(l >> 5) * Cq + nb + (l & 31)];
        }
        __syncthreads();
        float w = bw[sel];
        #pragma unroll
        for (int s = 0; s < 4; s++) {
            int i = ty + 8 * s;
            float acc = 0.f;
            #pragma unroll
            for (int r = 0; r < Rq; r++) acc = fmaf(las[i][r], lbs[r][tx], acc);
            ws[i][tx] = fmaf(w, acc, ws[i][tx]);
        }
    }
    __syncthreads();
    #pragma unroll
    for (int s = 0; s < 4; s++) {
        float v = ws[tx][ty + 8 * s];
        fp16 h, l; split_h(v, h, l);
        size_t idx = (size_t)(nb + ty + 8 * s) * Cq + kb + tx;
        dh[idx] = h; dl[idx] = l;
    }
}

// ---------------- pipelined fp16 GEMM core: 2-pass, 3 stages, 2 CTAs/SM ----------------
#define PITCH 40
#define NSTAGE 3
#define TILE_B 10240                       // 128*40*2
#define STAGE_B (3*TILE_B)                 // Ah, Bh, Bl
#define GEMM_DSMEM (NSTAGE*STAGE_B)        // 92160

__device__ __forceinline__ void issue_chunk(uint32_t sbase, int stage,
                                            const fp16* ah, const fp16* bh, const fp16* bl,
                                            int stride, int tid) {
    uint32_t st = sbase + stage * STAGE_B;
    const fp16* srcs[3] = {ah, bh, bl};
    #pragma unroll
    for (int t = 0; t < 3; t++) {
        #pragma unroll
        for (int i = 0; i < 2; i++) {
            int idx = tid + 256 * i;
            int row = idx >> 2, seg = idx & 3;
            cp16(st + t * TILE_B + (row * PITCH + seg * 8) * 2,
                 srcs[t] + (size_t)row * stride + seg * 8);
        }
    }
    cp_commit();
}

__device__ __forceinline__ void compute_chunk(uint32_t sbase, int stage,
                                              float C[2][8][4], int a_off, int b_off) {
    uint32_t st = sbase + stage * STAGE_B;
    uint32_t aH = st, bH = st + TILE_B, bL = st + 2 * TILE_B;
    #pragma unroll
    for (int kt = 0; kt < 2; kt++) {
        int ko = kt * 16;
        uint32_t ah[2][4], bh[8][2], bl[8][2];
        #pragma unroll
        for (int mt = 0; mt < 2; mt++) {
            int off = (a_off + mt * 16 * PITCH + ko) * 2;
            ldsm4(ah[mt][0], ah[mt][1], ah[mt][2], ah[mt][3], aH + off);
        }
        #pragma unroll
        for (int p = 0; p < 4; p++) {
            int off = (b_off + p * 16 * PITCH + ko) * 2;
            ldsm4(bh[2*p][0], bh[2*p][1], bh[2*p+1][0], bh[2*p+1][1], bH + off);
            ldsm4(bl[2*p][0], bl[2*p][1], bl[2*p+1][0], bl[2*p+1][1], bL + off);
        }
        #pragma unroll
        for (int mt = 0; mt < 2; mt++)
            #pragma unroll
            for (int nt = 0; nt < 8; nt++) {
                mma_f16(C[mt][nt], ah[mt][0], ah[mt][1], ah[mt][2], ah[mt][3],
                        bh[nt][0], bh[nt][1]);
                mma_f16(C[mt][nt], ah[mt][0], ah[mt][1], ah[mt][2], ah[mt][3],
                        bl[nt][0], bl[nt][1]);
            }
    }
}

// ---------------- qkv GEMM -> q single (scaled), k hi/lo, v single ----------------
__global__ __launch_bounds__(256, 2) void gemm_qkv_kernel() {
    extern __shared__ char dsm[];
    uint32_t sbase = smem_u32(dsm);
    int tid = threadIdx.x, lid = tid & 31, wid = tid >> 5;
    int wm = (wid & 3) * 32, wn = (wid >> 2) * 64;
    int type = blockIdx.z;
    int rowBase = blockIdx.y * 128, colBase = blockIdx.x * 128;

    const fp16* Xp = g_X16 + (size_t)rowBase * Cq;
    const fp16* Wh = g_Wth[type] + (size_t)colBase * Cq;
    const fp16* Wl = g_Wtl[type] + (size_t)colBase * Cq;

    float C[2][8][4];
    #pragma unroll
    for (int i = 0; i < 2; i++)
        #pragma unroll
        for (int j = 0; j < 8; j++)
            #pragma unroll
            for (int k = 0; k < 4; k++) C[i][j][k] = 0.f;

    int a_off = (wm + (lid & 15)) * PITCH + ((lid >> 4) & 1) * 8;
    int b_off = (wn + ((lid >> 4) & 1) * 8 + (lid & 7)) * PITCH + ((lid >> 3) & 1) * 8;

    const int NCH = 24;
    issue_chunk(sbase, 0, Xp, Wh, Wl, Cq, tid);
    issue_chunk(sbase, 1, Xp + 32, Wh + 32, Wl + 32, Cq, tid);
    for (int c = 0; c < NCH; c++) {
        cp_wait<1>();
        __syncthreads();
        int nc = c + 2;
        if (nc < NCH)
            issue_chunk(sbase, nc % 3, Xp + nc * 32, Wh + nc * 32, Wl + nc * 32, Cq, tid);
        else
            cp_commit();   // keep group count uniform for wait<1>
        compute_chunk(sbase, c % 3, C, a_off, b_off);
    }

    float scl = (type == 0) ? QSCALE : 1.f;
    #pragma unroll
    for (int mt = 0; mt < 2; mt++)
        #pragma unroll
        for (int nt = 0; nt < 8; nt++) {
            int col = colBase + wn + nt * 8 + (lid & 3) * 2;
            int h = col >> 6, hd = col & 63;
            #pragma unroll
            for (int half = 0; half < 2; half++) {
                int row = rowBase + wm + mt * 16 + (lid >> 2) + half * 8;
                int b_ = row >> 10, n = row & 1023;
                float v0 = C[mt][nt][half * 2] * scl, v1 = C[mt][nt][half * 2 + 1] * scl;
                size_t base = (((size_t)(b_ * Hq + h) * Nq) + n) * HDq + hd;
                if (type == 0) {
                    *(uint32_t*)&g_q[base] = pkh(v0, v1);
                } else if (type == 2) {
                    *(uint32_t*)&g_v[base] = pkh(v0, v1);
                } else {
                    fp16 h0, l0, h1, l1;
                    split_h(v0, h0, l0); split_h(v1, h1, l1);
                    __half2 th; th.x = h0; th.y = h1;
                    __half2 tl; tl.x = l0; tl.y = l1;
                    *(uint32_t*)&g_kh[base] = *(uint32_t*)&th;
                    *(uint32_t*)&g_kl[base] = *(uint32_t*)&tl;
                }
            }
        }
}

// ---------------- output projection GEMM + bias (att single, Wp hi/lo) ----------------
__global__ __launch_bounds__(256, 2) void gemm_out_kernel(const float* __restrict__ bias,
                                                          float* __restrict__ out) {
    extern __shared__ char dsm[];
    uint32_t sbase = smem_u32(dsm);
    int tid = threadIdx.x, lid = tid & 31, wid = tid >> 5;
    int wm = (wid & 3) * 32, wn = (wid >> 2) * 64;
    int rowBase = blockIdx.y * 128, colBase = blockIdx.x * 128;

    const fp16* Ap = g_att + (size_t)rowBase * Cq;
    const fp16* Wh = g_Wpth + (size_t)colBase * Cq;
    const fp16* Wl = g_Wptl + (size_t)colBase * Cq;

    float C[2][8][4];
    #pragma unroll
    for (int i = 0; i < 2; i++)
        #pragma unroll
        for (int j = 0; j < 8; j++)
            #pragma unroll
            for (int k = 0; k < 4; k++) C[i][j][k] = 0.f;

    int a_off = (wm + (lid & 15)) * PITCH + ((lid >> 4) & 1) * 8;
    int b_off = (wn + ((lid >> 4) & 1) * 8 + (lid & 7)) * PITCH + ((lid >> 3) & 1) * 8;

    const int NCH = 24;
    issue_chunk(sbase, 0, Ap, Wh, Wl, Cq, tid);
    issue_chunk(sbase, 1, Ap + 32, Wh + 32, Wl + 32, Cq, tid);
    for (int c = 0; c < NCH; c++) {
        cp_wait<1>();
        __syncthreads();
        int nc = c + 2;
        if (nc < NCH)
            issue_chunk(sbase, nc % 3, Ap + nc * 32, Wh + nc * 32, Wl + nc * 32, Cq, tid);
        else
            cp_commit();
        compute_chunk(sbase, c % 3, C, a_off, b_off);
    }

    #pragma unroll
    for (int mt = 0; mt < 2; mt++)
        #pragma unroll
        for (int nt = 0; nt < 8; nt++) {
            int col = colBase + wn + nt * 8 + (lid & 3) * 2;
            float2 bv = *(const float2*)&bias[col];
            #pragma unroll
            for (int half = 0; half < 2; half++) {
                int row = rowBase + wm + mt * 16 + (lid >> 2) + half * 8;
                float2 v = make_float2(C[mt][nt][half * 2] + bv.x, C[mt][nt][half * 2 + 1] + bv.y);
                *(float2*)&out[(size_t)row * Cq + col] = v;
            }
        }
}

// ---------------- FA2 attention: fp16, QK 2-pass, PV 1-pass, 3-stage KV pipeline ----------
#define KVP 72
#define QBYTES (128*KVP*2)               // 18432
#define KVT (64*KVP*2)                   // 9216
#define KVSTAGE (3*KVT)                  // Kh, Kl, Vh = 27648
#define AOFF_KV QBYTES
#define ATTN_SMEM (QBYTES + 3*KVSTAGE)   // 101376

__global__ __launch_bounds__(256, 2) void attn_kernel() {
    extern __shared__ char smx[];
    uint32_t sb = smem_u32(smx);
    int tid = threadIdx.x, lid = tid & 31, wid = tid >> 5;
    int wm = wid * 16;
    int qt = blockIdx.x, head = blockIdx.y, b = blockIdx.z;
    size_t bh = (size_t)(b * Hq + head) * Nq * HDq;
    const fp16* Qg = g_q + bh + (size_t)qt * 128 * HDq;

    // stage loader: Kh, Kl, Vh for tile 'kt' into stage slot
    auto load_stage = [&](int kt, int slot) {
        uint32_t dst = sb + AOFF_KV + slot * KVSTAGE;
        const fp16* srcs[3] = {g_kh + bh + (size_t)kt * 64 * HDq,
                               g_kl + bh + (size_t)kt * 64 * HDq,
                               g_v  + bh + (size_t)kt * 64 * HDq};
        #pragma unroll
        for (int t = 0; t < 3; t++)
            #pragma unroll
            for (int i = 0; i < 2; i++) {
                int idx = tid + 256 * i;
                int row = idx >> 3, seg = idx & 7;
                cp16(dst + t * KVT + (row * KVP + seg * 8) * 2,
                     srcs[t] + row * HDq + seg * 8);
            }
    };

    // prologue: Q (128 rows x 8 segs of 16B = full 128x64 fp16 tile) + stage0, stage1
    #pragma unroll
    for (int i = 0; i < 4; i++) {
        int idx = tid + 256 * i;
        int row = idx >> 3, seg = idx & 7;
        cp16(sb + (row * KVP + seg * 8) * 2, Qg + row * HDq + seg * 8);
    }
    load_stage(0, 0);
    cp_commit();
    load_stage(1, 1);
    cp_commit();

    float mA = -1e30f, mB = -1e30f, lA = 0.f, lB = 0.f;
    float co[8][4];
    #pragma unroll
    for (int j = 0; j < 8; j++)
        #pragma unroll
        for (int k = 0; k < 4; k++) co[j][k] = 0.f;

    for (int it = 0; it < 16; it++) {
        cp_wait<1>();
        __syncthreads();
        if (it + 2 < 16) { load_stage(it + 2, (it + 2) % 3); cp_commit(); }
        else cp_commit();

        uint32_t kv = sb + AOFF_KV + (it % 3) * KVSTAGE;
        uint32_t aKh = kv, aKl = kv + KVT, aVh = kv + 2 * KVT;

        // ---- S = Q K^T : 2-pass (q·kh + q·kl) ----
        float cs[8][4];
        #pragma unroll
        for (int j = 0; j < 8; j++)
            #pragma unroll
            for (int k = 0; k < 4; k++) cs[j][k] = 0.f;

        #pragma unroll
        for (int ks = 0; ks < 4; ks++) {
            int ko = ks * 16;
            uint32_t qh[4], kh[8][2], kl[8][2];
            int offq = ((wm + (lid & 15)) * KVP + ((lid >> 4) & 1) * 8 + ko) * 2;
            ldsm4(qh[0], qh[1], qh[2], qh[3], sb + offq);
            #pragma unroll
            for (int p = 0; p < 4; p++) {
                int offb = ((p * 16 + ((lid >> 4) & 1) * 8 + (lid & 7)) * KVP
                            + ((lid >> 3) & 1) * 8 + ko) * 2;
                ldsm4(kh[2*p][0], kh[2*p][1], kh[2*p+1][0], kh[2*p+1][1], aKh + offb);
                ldsm4(kl[2*p][0], kl[2*p][1], kl[2*p+1][0], kl[2*p+1][1], aKl + offb);
            }
            #pragma unroll
            for (int nt = 0; nt < 8; nt++) {
                mma_f16(cs[nt], qh[0], qh[1], qh[2], qh[3], kh[nt][0], kh[nt][1]);
                mma_f16(cs[nt], qh[0], qh[1], qh[2], qh[3], kl[nt][0], kl[nt][1]);
            }
        }

        // ---- register softmax (log2 domain), deferred l-reduction ----
        float mxA = -1e30f, mxB = -1e30f;
        #pragma unroll
        for (int nt = 0; nt < 8; nt++) {
            mxA = fmaxf(mxA, fmaxf(cs[nt][0], cs[nt][1]));
            mxB = fmaxf(mxB, fmaxf(cs[nt][2], cs[nt][3]));
        }
        mxA = fmaxf(mxA, __shfl_xor_sync(0xffffffffu, mxA, 1));
        mxA = fmaxf(mxA, __shfl_xor_sync(0xffffffffu, mxA, 2));
        mxB = fmaxf(mxB, __shfl_xor_sync(0xffffffffu, mxB, 1));
        mxB = fmaxf(mxB, __shfl_xor_sync(0xffffffffu, mxB, 2));
        float mnA = fmaxf(mA, mxA), mnB = fmaxf(mB, mxB);
        float alA = ex2(mA - mnA), alB = ex2(mB - mnB);
        float psA = 0.f, psB = 0.f;
        #pragma unroll
        for (int nt = 0; nt < 8; nt++) {
            cs[nt][0] = ex2(cs[nt][0] - mnA);
            cs[nt][1] = ex2(cs[nt][1] - mnA);
            cs[nt][2] = ex2(cs[nt][2] - mnB);
            cs[nt][3] = ex2(cs[nt][3] - mnB);
            psA += cs[nt][0] + cs[nt][1];
            psB += cs[nt][2] + cs[nt][3];
        }
        lA = lA * alA + psA; mA = mnA;
        lB = lB * alB + psB; mB = mnB;

        // ---- repack P c-frags -> a-frags (fp16 single) ----
        uint32_t pa[4][4];
        #pragma unroll
        for (int ks = 0; ks < 4; ks++) {
            #pragma unroll
            for (int half = 0; half < 2; half++) {
                int nt = 2 * ks + half;
                pa[ks][2 * half]     = pkh(cs[nt][0], cs[nt][1]);
                pa[ks][2 * half + 1] = pkh(cs[nt][2], cs[nt][3]);
            }
        }

        // ---- rescale O, O += P V (1-pass) ----
        #pragma unroll
        for (int nt = 0; nt < 8; nt++) {
            co[nt][0] *= alA; co[nt][1] *= alA;
            co[nt][2] *= alB; co[nt][3] *= alB;
        }
        #pragma unroll
        for (int ks = 0; ks < 4; ks++) {
            int ko = ks * 16;
            uint32_t vh[8][2];
            #pragma unroll
            for (int dt = 0; dt < 4; dt++) {
                int offv = ((ko + (lid & 15)) * KVP + dt * 16 + ((lid >> 4) & 1) * 8) * 2;
                ldsm4t(vh[2*dt][0], vh[2*dt][1], vh[2*dt+1][0], vh[2*dt+1][1], aVh + offv);
            }
            #pragma unroll
            for (int nt = 0; nt < 8; nt++)
                mma_f16(co[nt], pa[ks][0], pa[ks][1], pa[ks][2], pa[ks][3],
                        vh[nt][0], vh[nt][1]);
        }
    }

    // final l reduction across the 4 lanes sharing each row
    lA += __shfl_xor_sync(0xffffffffu, lA, 1);
    lA += __shfl_xor_sync(0xffffffffu, lA, 2);
    lB += __shfl_xor_sync(0xffffffffu, lB, 1);
    lB += __shfl_xor_sync(0xffffffffu, lB, 2);

    // epilogue: normalize, write fp16 att [B,N,C]
    float invA = 1.f / lA, invB = 1.f / lB;
    int rA = qt * 128 + wm + (lid >> 2);
    #pragma unroll
    for (int nt = 0; nt < 8; nt++) {
        int col = head * HDq + nt * 8 + (lid & 3) * 2;
        size_t base = (size_t)(b * Nq + rA) * Cq + col;
        *(uint32_t*)&g_att[base] = pkh(co[nt][0] * invA, co[nt][1] * invA);
        size_t base2 = (size_t)(b * Nq + rA + 8) * Cq + col;
        *(uint32_t*)&g_att[base2] = pkh(co[nt][2] * invB, co[nt][3] * invB);
    }
}

extern "C" void kernel_launch(void* const* d_in, const int* in_sizes, int n_in,
                              void* d_out, int out_size) {
    const float* x    = (const float*)d_in[0];
    const float* Wq   = (const float*)d_in[1];
    const float* Wk   = (const float*)d_in[2];
    const float* Wv   = (const float*)d_in[3];
    const float* Wp   = (const float*)d_in[4];
    const float* bp   = (const float*)d_in[5];
    const float* la_q = (const float*)d_in[6];
    const float* lb_q = (const float*)d_in[7];
    const float* la_k = (const float*)d_in[8];
    const float* lb_k = (const float*)d_in[9];
    const float* la_v = (const float*)d_in[10];
    const float* lb_v = (const float*)d_in[11];
    const float* bw   = (const float*)d_in[12];
    float* out = (float*)d_out;

    convert_x_kernel<<<(ROWS * Cq + 255) / 256, 256>>>(x);
    wprime_kernel<<<dim3(24, 24, 4), 256>>>(Wq, Wk, Wv, Wp,
                                            la_q, lb_q, la_k, lb_k, la_v, lb_v, bw);

    cudaFuncSetAttribute(gemm_qkv_kernel, cudaFuncAttributeMaxDynamicSharedMemorySize, GEMM_DSMEM);
    gemm_qkv_kernel<<<dim3(6, 64, 3), 256, GEMM_DSMEM>>>();

    cudaFuncSetAttribute(attn_kernel, cudaFuncAttributeMaxDynamicSharedMemorySize, ATTN_SMEM);
    attn_kernel<<<dim3(Nq / 128, Hq, Bq), 256, ATTN_SMEM>>>();

    cudaFuncSetAttribute(gemm_out_kernel, cudaFuncAttributeMaxDynamicSharedMemorySize, GEMM_DSMEM);
    gemm_out_kernel<<<dim3(6, 64), 256, GEMM_DSMEM>>>(bp, out);
}

// round 12
// speedup vs baseline: 1.5866x; 1.0259x over previous
#include <cuda_runtime.h>
#include <cuda_fp16.h>
#include <cstdint>

#define Bq 8
#define Nq 1024
#define Cq 768
#define Hq 12
#define HDq 64
#define Rq 16
#define ROWS (Bq*Nq)
#define QSCALE 0.18033688011112042f   // 0.125 * log2(e)

typedef __half fp16;

// ---------------- helpers ----------------
__device__ __forceinline__ uint32_t smem_u32(const void* p) {
    uint32_t a;
    asm("{ .reg .u64 t; cvta.to.shared.u64 t, %1; cvt.u32.u64 %0, t; }" : "=r"(a) : "l"(p));
    return a;
}
__device__ __forceinline__ void ldsm4(uint32_t& r0, uint32_t& r1, uint32_t& r2, uint32_t& r3,
                                      uint32_t addr) {
    asm volatile("ldmatrix.sync.aligned.m8n8.x4.shared.b16 {%0,%1,%2,%3}, [%4];"
                 : "=r"(r0), "=r"(r1), "=r"(r2), "=r"(r3) : "r"(addr));
}
__device__ __forceinline__ void ldsm4t(uint32_t& r0, uint32_t& r1, uint32_t& r2, uint32_t& r3,
                                       uint32_t addr) {
    asm volatile("ldmatrix.sync.aligned.m8n8.x4.trans.shared.b16 {%0,%1,%2,%3}, [%4];"
                 : "=r"(r0), "=r"(r1), "=r"(r2), "=r"(r3) : "r"(addr));
}
__device__ __forceinline__ void mma_f16(float* c, uint32_t a0, uint32_t a1, uint32_t a2,
                                        uint32_t a3, uint32_t b0, uint32_t b1) {
    asm("mma.sync.aligned.m16n8k16.row.col.f32.f16.f16.f32 "
        "{%0,%1,%2,%3}, {%4,%5,%6,%7}, {%8,%9}, {%0,%1,%2,%3};"
        : "+f"(c[0]), "+f"(c[1]), "+f"(c[2]), "+f"(c[3])
        : "r"(a0), "r"(a1), "r"(a2), "r"(a3), "r"(b0), "r"(b1));
}
__device__ __forceinline__ void cp16(uint32_t dst, const void* src) {
    asm volatile("cp.async.cg.shared.global [%0], [%1], 16;" :: "r"(dst), "l"(src));
}
__device__ __forceinline__ void cp_commit() {
    asm volatile("cp.async.commit_group;" ::: "memory");
}
template <int N>
__device__ __forceinline__ void cp_wait() {
    asm volatile("cp.async.wait_group %0;" :: "n"(N) : "memory");
}
__device__ __forceinline__ float ex2(float x) {
    float y; asm("ex2.approx.f32 %0, %1;" : "=f"(y) : "f"(x)); return y;
}
__device__ __forceinline__ uint32_t pkh(float a, float b) {
    __half2 t = __floats2half2_rn(a, b);
    return *(uint32_t*)&t;
}
__device__ __forceinline__ void split_h(float v, fp16& h, fp16& l) {
    h = __float2half_rn(v);
    l = __float2half_rn(v - __half2float(h));
}

// ---------------- scratch ----------------
__device__ fp16 g_q[Bq*Hq*Nq*HDq];                    // single, pre-scaled
__device__ fp16 g_kh[Bq*Hq*Nq*HDq], g_kl[Bq*Hq*Nq*HDq];
__device__ fp16 g_v[Bq*Hq*Nq*HDq];                    // single
__device__ fp16 g_X16[ROWS*Cq];                       // single
__device__ fp16 g_Wth[3][Cq*Cq], g_Wtl[3][Cq*Cq];     // (W + bw*la@lb)^T hi/lo
__device__ fp16 g_Wpth[Cq*Cq], g_Wptl[Cq*Cq];
__device__ fp16 g_att[ROWS*Cq];                       // single

// ---------------- prep kernels ----------------
__global__ void convert_x_kernel(const float* __restrict__ X) {
    int i = blockIdx.x * blockDim.x + threadIdx.x;
    if (i < ROWS * Cq) g_X16[i] = __float2half_rn(X[i]);
}

// W' = W + bw*(la@lb)  (sel<3), or plain Wp (sel=3); write transposed hi/lo fp16
__global__ __launch_bounds__(256) void wprime_kernel(
        const float* __restrict__ Wq_, const float* __restrict__ Wk_,
        const float* __restrict__ Wv_, const float* __restrict__ Wp_,
        const float* __restrict__ laq, const float* __restrict__ lbq,
        const float* __restrict__ lak, const float* __restrict__ lbk,
        const float* __restrict__ lav, const float* __restrict__ lbv,
        const float* __restrict__ bw) {
    __shared__ float ws[32][33];
    __shared__ float las[32][16];
    __shared__ float lbs[16][33];
    int sel = blockIdx.z;
    const float* W  = (sel == 0) ? Wq_ : (sel == 1) ? Wk_ : (sel == 2) ? Wv_ : Wp_;
    const float* la = (sel == 0) ? laq : (sel == 1) ? lak : lav;
    const float* lb = (sel == 0) ? lbq : (sel == 1) ? lbk : lbv;
    fp16* dh = (sel < 3) ? g_Wth[sel] : g_Wpth;
    fp16* dl = (sel < 3) ? g_Wtl[sel] : g_Wptl;
    int tid = threadIdx.x, tx = tid & 31, ty = tid >> 5;
    int kb = blockIdx.y * 32, nb = blockIdx.x * 32;
    #pragma unroll
    for (int s = 0; s < 4; s++)
        ws[ty + 8 * s][tx] = W[(size_t)(kb + ty + 8 * s) * Cq + nb + tx];
    if (sel < 3) {
        for (int l = tid; l < 512; l += 256) {
            las[l >> 4][l & 15] = la[(size_t)(kb + (l >> 4)) * Rq + (l & 15)];
            lbs[l >> 5][l & 31] = lb[(size_t)(l >> 5) * Cq + nb + (l & 31)];
        }
        __syncthreads();
        float w = bw[sel];
        #pragma unroll
        for (int s = 0; s < 4; s++) {
            int i = ty + 8 * s;
            float acc = 0.f;
            #pragma unroll
            for (int r = 0; r < Rq; r++) acc = fmaf(las[i][r], lbs[r][tx], acc);
            ws[i][tx] = fmaf(w, acc, ws[i][tx]);
        }
    }
    __syncthreads();
    #pragma unroll
    for (int s = 0; s < 4; s++) {
        float v = ws[tx][ty + 8 * s];
        fp16 h, l; split_h(v, h, l);
        size_t idx = (size_t)(nb + ty + 8 * s) * Cq + kb + tx;
        dh[idx] = h; dl[idx] = l;
    }
}

// ---------------- pipelined fp16 GEMM core: 3 stages, 2 CTAs/SM ----------------
#define PITCH 40
#define NSTAGE 3
#define TILE_B 10240                       // 128*40*2
#define STAGE_B (3*TILE_B)                 // Ah, Bh, Bl
#define GEMM_DSMEM (NSTAGE*STAGE_B)        // 92160

__device__ __forceinline__ void issue_chunk(uint32_t sbase, int stage,
                                            const fp16* ah, const fp16* bh, const fp16* bl,
                                            int stride, int tid, bool twop) {
    uint32_t st = sbase + stage * STAGE_B;
    const fp16* srcs[3] = {ah, bh, bl};
    int ntiles = twop ? 3 : 2;
    for (int t = 0; t < ntiles; t++) {
        #pragma unroll
        for (int i = 0; i < 2; i++) {
            int idx = tid + 256 * i;
            int row = idx >> 2, seg = idx & 3;
            cp16(st + t * TILE_B + (row * PITCH + seg * 8) * 2,
                 srcs[t] + (size_t)row * stride + seg * 8);
        }
    }
    cp_commit();
}

__device__ __forceinline__ void compute_chunk(uint32_t sbase, int stage,
                                              float C[2][8][4], int a_off, int b_off,
                                              bool twop) {
    uint32_t st = sbase + stage * STAGE_B;
    uint32_t aH = st, bH = st + TILE_B, bL = st + 2 * TILE_B;
    #pragma unroll
    for (int kt = 0; kt < 2; kt++) {
        int ko = kt * 16;
        uint32_t ah[2][4], bh[8][2], bl[8][2];
        #pragma unroll
        for (int mt = 0; mt < 2; mt++) {
            int off = (a_off + mt * 16 * PITCH + ko) * 2;
            ldsm4(ah[mt][0], ah[mt][1], ah[mt][2], ah[mt][3], aH + off);
        }
        #pragma unroll
        for (int p = 0; p < 4; p++) {
            int off = (b_off + p * 16 * PITCH + ko) * 2;
            ldsm4(bh[2*p][0], bh[2*p][1], bh[2*p+1][0], bh[2*p+1][1], bH + off);
        }
        if (twop) {
            #pragma unroll
            for (int p = 0; p < 4; p++) {
                int off = (b_off + p * 16 * PITCH + ko) * 2;
                ldsm4(bl[2*p][0], bl[2*p][1], bl[2*p+1][0], bl[2*p+1][1], bL + off);
            }
        }
        #pragma unroll
        for (int mt = 0; mt < 2; mt++)
            #pragma unroll
            for (int nt = 0; nt < 8; nt++) {
                mma_f16(C[mt][nt], ah[mt][0], ah[mt][1], ah[mt][2], ah[mt][3],
                        bh[nt][0], bh[nt][1]);
                if (twop)
                    mma_f16(C[mt][nt], ah[mt][0], ah[mt][1], ah[mt][2], ah[mt][3],
                            bl[nt][0], bl[nt][1]);
            }
    }
}

// ---------------- qkv GEMM: q,v 1-pass; k 2-pass ----------------
__global__ __launch_bounds__(256, 2) void gemm_qkv_kernel() {
    extern __shared__ char dsm[];
    uint32_t sbase = smem_u32(dsm);
    int tid = threadIdx.x, lid = tid & 31, wid = tid >> 5;
    int wm = (wid & 3) * 32, wn = (wid >> 2) * 64;
    int type = blockIdx.z;
    bool twop = (type == 1);
    int rowBase = blockIdx.y * 128, colBase = blockIdx.x * 128;

    const fp16* Xp = g_X16 + (size_t)rowBase * Cq;
    const fp16* Wh = g_Wth[type] + (size_t)colBase * Cq;
    const fp16* Wl = g_Wtl[type] + (size_t)colBase * Cq;

    float C[2][8][4];
    #pragma unroll
    for (int i = 0; i < 2; i++)
        #pragma unroll
        for (int j = 0; j < 8; j++)
            #pragma unroll
            for (int k = 0; k < 4; k++) C[i][j][k] = 0.f;

    int a_off = (wm + (lid & 15)) * PITCH + ((lid >> 4) & 1) * 8;
    int b_off = (wn + ((lid >> 4) & 1) * 8 + (lid & 7)) * PITCH + ((lid >> 3) & 1) * 8;

    const int NCH = 24;
    issue_chunk(sbase, 0, Xp, Wh, Wl, Cq, tid, twop);
    issue_chunk(sbase, 1, Xp + 32, Wh + 32, Wl + 32, Cq, tid, twop);
    for (int c = 0; c < NCH; c++) {
        cp_wait<1>();
        __syncthreads();
        int nc = c + 2;
        if (nc < NCH)
            issue_chunk(sbase, nc % 3, Xp + nc * 32, Wh + nc * 32, Wl + nc * 32, Cq, tid, twop);
        else
            cp_commit();   // keep group count uniform for wait<1>
        compute_chunk(sbase, c % 3, C, a_off, b_off, twop);
    }

    float scl = (type == 0) ? QSCALE : 1.f;
    #pragma unroll
    for (int mt = 0; mt < 2; mt++)
        #pragma unroll
        for (int nt = 0; nt < 8; nt++) {
            int col = colBase + wn + nt * 8 + (lid & 3) * 2;
            int h = col >> 6, hd = col & 63;
            #pragma unroll
            for (int half = 0; half < 2; half++) {
                int row = rowBase + wm + mt * 16 + (lid >> 2) + half * 8;
                int b_ = row >> 10, n = row & 1023;
                float v0 = C[mt][nt][half * 2] * scl, v1 = C[mt][nt][half * 2 + 1] * scl;
                size_t base = (((size_t)(b_ * Hq + h) * Nq) + n) * HDq + hd;
                if (type == 0) {
                    *(uint32_t*)&g_q[base] = pkh(v0, v1);
                } else if (type == 2) {
                    *(uint32_t*)&g_v[base] = pkh(v0, v1);
                } else {
                    fp16 h0, l0, h1, l1;
                    split_h(v0, h0, l0); split_h(v1, h1, l1);
                    __half2 th; th.x = h0; th.y = h1;
                    __half2 tl; tl.x = l0; tl.y = l1;
                    *(uint32_t*)&g_kh[base] = *(uint32_t*)&th;
                    *(uint32_t*)&g_kl[base] = *(uint32_t*)&tl;
                }
            }
        }
}

// ---------------- output projection GEMM + bias (att single, Wp hi/lo) ----------------
__global__ __launch_bounds__(256, 2) void gemm_out_kernel(const float* __restrict__ bias,
                                                          float* __restrict__ out) {
    extern __shared__ char dsm[];
    uint32_t sbase = smem_u32(dsm);
    int tid = threadIdx.x, lid = tid & 31, wid = tid >> 5;
    int wm = (wid & 3) * 32, wn = (wid >> 2) * 64;
    int rowBase = blockIdx.y * 128, colBase = blockIdx.x * 128;

    const fp16* Ap = g_att + (size_t)rowBase * Cq;
    const fp16* Wh = g_Wpth + (size_t)colBase * Cq;
    const fp16* Wl = g_Wptl + (size_t)colBase * Cq;

    float C[2][8][4];
    #pragma unroll
    for (int i = 0; i < 2; i++)
        #pragma unroll
        for (int j = 0; j < 8; j++)
            #pragma unroll
            for (int k = 0; k < 4; k++) C[i][j][k] = 0.f;

    int a_off = (wm + (lid & 15)) * PITCH + ((lid >> 4) & 1) * 8;
    int b_off = (wn + ((lid >> 4) & 1) * 8 + (lid & 7)) * PITCH + ((lid >> 3) & 1) * 8;

    const int NCH = 24;
    issue_chunk(sbase, 0, Ap, Wh, Wl, Cq, tid, true);
    issue_chunk(sbase, 1, Ap + 32, Wh + 32, Wl + 32, Cq, tid, true);
    for (int c = 0; c < NCH; c++) {
        cp_wait<1>();
        __syncthreads();
        int nc = c + 2;
        if (nc < NCH)
            issue_chunk(sbase, nc % 3, Ap + nc * 32, Wh + nc * 32, Wl + nc * 32, Cq, tid, true);
        else
            cp_commit();
        compute_chunk(sbase, c % 3, C, a_off, b_off, true);
    }

    #pragma unroll
    for (int mt = 0; mt < 2; mt++)
        #pragma unroll
        for (int nt = 0; nt < 8; nt++) {
            int col = colBase + wn + nt * 8 + (lid & 3) * 2;
            float2 bv = *(const float2*)&bias[col];
            #pragma unroll
            for (int half = 0; half < 2; half++) {
                int row = rowBase + wm + mt * 16 + (lid >> 2) + half * 8;
                float2 v = make_float2(C[mt][nt][half * 2] + bv.x, C[mt][nt][half * 2 + 1] + bv.y);
                *(float2*)&out[(size_t)row * Cq + col] = v;
            }
        }
}

// ---------------- FA2 attention: fp16, QK 2-pass, PV 1-pass, 3-stage KV pipeline ----------
#define KVP 72
#define QBYTES (128*KVP*2)               // 18432
#define KVT (64*KVP*2)                   // 9216
#define KVSTAGE (3*KVT)                  // Kh, Kl, Vh = 27648
#define AOFF_KV QBYTES
#define ATTN_SMEM (QBYTES + 3*KVSTAGE)   // 101376

__global__ __launch_bounds__(256, 2) void attn_kernel() {
    extern __shared__ char smx[];
    uint32_t sb = smem_u32(smx);
    int tid = threadIdx.x, lid = tid & 31, wid = tid >> 5;
    int wm = wid * 16;
    int qt = blockIdx.x, head = blockIdx.y, b = blockIdx.z;
    size_t bh = (size_t)(b * Hq + head) * Nq * HDq;
    const fp16* Qg = g_q + bh + (size_t)qt * 128 * HDq;

    // stage loader: Kh, Kl, Vh for tile 'kt' into stage slot
    auto load_stage = [&](int kt, int slot) {
        uint32_t dst = sb + AOFF_KV + slot * KVSTAGE;
        const fp16* srcs[3] = {g_kh + bh + (size_t)kt * 64 * HDq,
                               g_kl + bh + (size_t)kt * 64 * HDq,
                               g_v  + bh + (size_t)kt * 64 * HDq};
        #pragma unroll
        for (int t = 0; t < 3; t++)
            #pragma unroll
            for (int i = 0; i < 2; i++) {
                int idx = tid + 256 * i;
                int row = idx >> 3, seg = idx & 7;
                cp16(dst + t * KVT + (row * KVP + seg * 8) * 2,
                     srcs[t] + row * HDq + seg * 8);
            }
    };

    // prologue: Q (128 rows x 8 segs of 16B) + stage0, stage1
    #pragma unroll
    for (int i = 0; i < 4; i++) {
        int idx = tid + 256 * i;
        int row = idx >> 3, seg = idx & 7;
        cp16(sb + (row * KVP + seg * 8) * 2, Qg + row * HDq + seg * 8);
    }
    load_stage(0, 0);
    cp_commit();
    load_stage(1, 1);
    cp_commit();

    float mA = -1e30f, mB = -1e30f, lA = 0.f, lB = 0.f;
    float co[8][4];
    #pragma unroll
    for (int j = 0; j < 8; j++)
        #pragma unroll
        for (int k = 0; k < 4; k++) co[j][k] = 0.f;

    uint32_t qfrag[4][4];                 // loop-invariant Q fragments

    for (int it = 0; it < 16; it++) {
        cp_wait<1>();
        __syncthreads();
        if (it == 0) {
            // hoist Q fragments (valid for whole loop)
            #pragma unroll
            for (int ks = 0; ks < 4; ks++) {
                int offq = ((wm + (lid & 15)) * KVP + ((lid >> 4) & 1) * 8 + ks * 16) * 2;
                ldsm4(qfrag[ks][0], qfrag[ks][1], qfrag[ks][2], qfrag[ks][3], sb + offq);
            }
        }
        if (it + 2 < 16) { load_stage(it + 2, (it + 2) % 3); cp_commit(); }
        else cp_commit();

        uint32_t kv = sb + AOFF_KV + (it % 3) * KVSTAGE;
        uint32_t aKh = kv, aKl = kv + KVT, aVh = kv + 2 * KVT;

        // ---- S = Q K^T : 2-pass (q·kh + q·kl) ----
        float cs[8][4];
        #pragma unroll
        for (int j = 0; j < 8; j++)
            #pragma unroll
            for (int k = 0; k < 4; k++) cs[j][k] = 0.f;

        #pragma unroll
        for (int ks = 0; ks < 4; ks++) {
            int ko = ks * 16;
            uint32_t kh[8][2], kl[8][2];
            #pragma unroll
            for (int p = 0; p < 4; p++) {
                int offb = ((p * 16 + ((lid >> 4) & 1) * 8 + (lid & 7)) * KVP
                            + ((lid >> 3) & 1) * 8 + ko) * 2;
                ldsm4(kh[2*p][0], kh[2*p][1], kh[2*p+1][0], kh[2*p+1][1], aKh + offb);
                ldsm4(kl[2*p][0], kl[2*p][1], kl[2*p+1][0], kl[2*p+1][1], aKl + offb);
            }
            #pragma unroll
            for (int nt = 0; nt < 8; nt++) {
                mma_f16(cs[nt], qfrag[ks][0], qfrag[ks][1], qfrag[ks][2], qfrag[ks][3],
                        kh[nt][0], kh[nt][1]);
                mma_f16(cs[nt], qfrag[ks][0], qfrag[ks][1], qfrag[ks][2], qfrag[ks][3],
                        kl[nt][0], kl[nt][1]);
            }
        }

        // ---- register softmax (log2 domain), deferred l-reduction ----
        float mxA = -1e30f, mxB = -1e30f;
        #pragma unroll
        for (int nt = 0; nt < 8; nt++) {
            mxA = fmaxf(mxA, fmaxf(cs[nt][0], cs[nt][1]));
            mxB = fmaxf(mxB, fmaxf(cs[nt][2], cs[nt][3]));
        }
        mxA = fmaxf(mxA, __shfl_xor_sync(0xffffffffu, mxA, 1));
        mxA = fmaxf(mxA, __shfl_xor_sync(0xffffffffu, mxA, 2));
        mxB = fmaxf(mxB, __shfl_xor_sync(0xffffffffu, mxB, 1));
        mxB = fmaxf(mxB, __shfl_xor_sync(0xffffffffu, mxB, 2));
        float mnA = fmaxf(mA, mxA), mnB = fmaxf(mB, mxB);
        float alA = ex2(mA - mnA), alB = ex2(mB - mnB);
        float psA = 0.f, psB = 0.f;
        #pragma unroll
        for (int nt = 0; nt < 8; nt++) {
            cs[nt][0] = ex2(cs[nt][0] - mnA);
            cs[nt][1] = ex2(cs[nt][1] - mnA);
            cs[nt][2] = ex2(cs[nt][2] - mnB);
            cs[nt][3] = ex2(cs[nt][3] - mnB);
            psA += cs[nt][0] + cs[nt][1];
            psB += cs[nt][2] + cs[nt][3];
        }
        lA = lA * alA + psA; mA = mnA;
        lB = lB * alB + psB; mB = mnB;

        // ---- repack P c-frags -> a-frags (fp16 single) ----
        uint32_t pa[4][4];
        #pragma unroll
        for (int ks = 0; ks < 4; ks++) {
            #pragma unroll
            for (int half = 0; half < 2; half++) {
                int nt = 2 * ks + half;
                pa[ks][2 * half]     = pkh(cs[nt][0], cs[nt][1]);
                pa[ks][2 * half + 1] = pkh(cs[nt][2], cs[nt][3]);
            }
        }

        // ---- rescale O, O += P V (1-pass) ----
        #pragma unroll
        for (int nt = 0; nt < 8; nt++) {
            co[nt][0] *= alA; co[nt][1] *= alA;
            co[nt][2] *= alB; co[nt][3] *= alB;
        }
        #pragma unroll
        for (int ks = 0; ks < 4; ks++) {
            int ko = ks * 16;
            uint32_t vh[8][2];
            #pragma unroll
            for (int dt = 0; dt < 4; dt++) {
                int offv = ((ko + (lid & 15)) * KVP + dt * 16 + ((lid >> 4) & 1) * 8) * 2;
                ldsm4t(vh[2*dt][0], vh[2*dt][1], vh[2*dt+1][0], vh[2*dt+1][1], aVh + offv);
            }
            #pragma unroll
            for (int nt = 0; nt < 8; nt++)
                mma_f16(co[nt], pa[ks][0], pa[ks][1], pa[ks][2], pa[ks][3],
                        vh[nt][0], vh[nt][1]);
        }
    }

    // final l reduction across the 4 lanes sharing each row
    lA += __shfl_xor_sync(0xffffffffu, lA, 1);
    lA += __shfl_xor_sync(0xffffffffu, lA, 2);
    lB += __shfl_xor_sync(0xffffffffu, lB, 1);
    lB += __shfl_xor_sync(0xffffffffu, lB, 2);

    // epilogue: normalize, write fp16 att [B,N,C]
    float invA = 1.f / lA, invB = 1.f / lB;
    int rA = qt * 128 + wm + (lid >> 2);
    #pragma unroll
    for (int nt = 0; nt < 8; nt++) {
        int col = head * HDq + nt * 8 + (lid & 3) * 2;
        size_t base = (size_t)(b * Nq + rA) * Cq + col;
        *(uint32_t*)&g_att[base] = pkh(co[nt][0] * invA, co[nt][1] * invA);
        size_t base2 = (size_t)(b * Nq + rA + 8) * Cq + col;
        *(uint32_t*)&g_att[base2] = pkh(co[nt][2] * invB, co[nt][3] * invB);
    }
}

extern "C" void kernel_launch(void* const* d_in, const int* in_sizes, int n_in,
                              void* d_out, int out_size) {
    const float* x    = (const float*)d_in[0];
    const float* Wq   = (const float*)d_in[1];
    const float* Wk   = (const float*)d_in[2];
    const float* Wv   = (const float*)d_in[3];
    const float* Wp   = (const float*)d_in[4];
    const float* bp   = (const float*)d_in[5];
    const float* la_q = (const float*)d_in[6];
    const float* lb_q = (const float*)d_in[7];
    const float* la_k = (const float*)d_in[8];
    const float* lb_k = (const float*)d_in[9];
    const float* la_v = (const float*)d_in[10];
    const float* lb_v = (const float*)d_in[11];
    const float* bw   = (const float*)d_in[12];
    float* out = (float*)d_out;

    convert_x_kernel<<<(ROWS * Cq + 255) / 256, 256>>>(x);
    wprime_kernel<<<dim3(24, 24, 4), 256>>>(Wq, Wk, Wv, Wp,
                                            la_q, lb_q, la_k, lb_k, la_v, lb_v, bw);

    cudaFuncSetAttribute(gemm_qkv_kernel, cudaFuncAttributeMaxDynamicSharedMemorySize, GEMM_DSMEM);
    gemm_qkv_kernel<<<dim3(6, 64, 3), 256, GEMM_DSMEM>>>();

    cudaFuncSetAttribute(attn_kernel, cudaFuncAttributeMaxDynamicSharedMemorySize, ATTN_SMEM);
    attn_kernel<<<dim3(Nq / 128, Hq, Bq), 256, ATTN_SMEM>>>();

    cudaFuncSetAttribute(gemm_out_kernel, cudaFuncAttributeMaxDynamicSharedMemorySize, GEMM_DSMEM);
    gemm_out_kernel<<<dim3(6, 64), 256, GEMM_DSMEM>>>(bp, out);
}

// round 13
// speedup vs baseline: 2.1092x; 1.3293x over previous
#include <cuda_runtime.h>
#include <cuda_fp16.h>
#include <cstdint>

#define Bq 8
#define Nq 1024
#define Cq 768
#define Hq 12
#define HDq 64
#define Rq 16
#define ROWS (Bq*Nq)
#define QSCALE 0.18033688011112042f   // 0.125 * log2(e)

typedef __half fp16;

// ---------------- helpers ----------------
__device__ __forceinline__ uint32_t smem_u32(const void* p) {
    uint32_t a;
    asm("{ .reg .u64 t; cvta.to.shared.u64 t, %1; cvt.u32.u64 %0, t; }" : "=r"(a) : "l"(p));
    return a;
}
__device__ __forceinline__ void ldsm4(uint32_t& r0, uint32_t& r1, uint32_t& r2, uint32_t& r3,
                                      uint32_t addr) {
    asm volatile("ldmatrix.sync.aligned.m8n8.x4.shared.b16 {%0,%1,%2,%3}, [%4];"
                 : "=r"(r0), "=r"(r1), "=r"(r2), "=r"(r3) : "r"(addr));
}
__device__ __forceinline__ void ldsm4t(uint32_t& r0, uint32_t& r1, uint32_t& r2, uint32_t& r3,
                                       uint32_t addr) {
    asm volatile("ldmatrix.sync.aligned.m8n8.x4.trans.shared.b16 {%0,%1,%2,%3}, [%4];"
                 : "=r"(r0), "=r"(r1), "=r"(r2), "=r"(r3) : "r"(addr));
}
__device__ __forceinline__ void mma_f16(float* c, uint32_t a0, uint32_t a1, uint32_t a2,
                                        uint32_t a3, uint32_t b0, uint32_t b1) {
    asm("mma.sync.aligned.m16n8k16.row.col.f32.f16.f16.f32 "
        "{%0,%1,%2,%3}, {%4,%5,%6,%7}, {%8,%9}, {%0,%1,%2,%3};"
        : "+f"(c[0]), "+f"(c[1]), "+f"(c[2]), "+f"(c[3])
        : "r"(a0), "r"(a1), "r"(a2), "r"(a3), "r"(b0), "r"(b1));
}
__device__ __forceinline__ void cp16(uint32_t dst, const void* src) {
    asm volatile("cp.async.cg.shared.global [%0], [%1], 16;" :: "r"(dst), "l"(src));
}
__device__ __forceinline__ void cp_commit() {
    asm volatile("cp.async.commit_group;" ::: "memory");
}
template <int N>
__device__ __forceinline__ void cp_wait() {
    asm volatile("cp.async.wait_group %0;" :: "n"(N) : "memory");
}
__device__ __forceinline__ float ex2(float x) {
    float y; asm("ex2.approx.f32 %0, %1;" : "=f"(y) : "f"(x)); return y;
}
__device__ __forceinline__ uint32_t pkh(float a, float b) {
    __half2 t = __floats2half2_rn(a, b);
    return *(uint32_t*)&t;
}
__device__ __forceinline__ void split_h(float v, fp16& h, fp16& l) {
    h = __float2half_rn(v);
    l = __float2half_rn(v - __half2float(h));
}

// ---------------- scratch ----------------
__device__ fp16 g_q[Bq*Hq*Nq*HDq];                    // single, pre-scaled by QSCALE
__device__ fp16 g_k[Bq*Hq*Nq*HDq];                    // single
__device__ fp16 g_v[Bq*Hq*Nq*HDq];                    // single
__device__ fp16 g_X16[ROWS*Cq];                       // single
__device__ fp16 g_Wth[3][Cq*Cq], g_Wtl[3][Cq*Cq];     // (W + bw*la@lb)^T hi/lo
__device__ fp16 g_Wpth[Cq*Cq], g_Wptl[Cq*Cq];
__device__ fp16 g_att[ROWS*Cq];                       // single

// ---------------- prep kernels ----------------
__global__ void convert_x_kernel(const float* __restrict__ X) {
    int i = blockIdx.x * blockDim.x + threadIdx.x;
    if (i < ROWS * Cq) g_X16[i] = __float2half_rn(X[i]);
}

// W' = W + bw*(la@lb)  (sel<3), or plain Wp (sel=3); write transposed hi/lo fp16
__global__ __launch_bounds__(256) void wprime_kernel(
        const float* __restrict__ Wq_, const float* __restrict__ Wk_,
        const float* __restrict__ Wv_, const float* __restrict__ Wp_,
        const float* __restrict__ laq, const float* __restrict__ lbq,
        const float* __restrict__ lak, const float* __restrict__ lbk,
        const float* __restrict__ lav, const float* __restrict__ lbv,
        const float* __restrict__ bw) {
    __shared__ float ws[32][33];
    __shared__ float las[32][16];
    __shared__ float lbs[16][33];
    int sel = blockIdx.z;
    const float* W  = (sel == 0) ? Wq_ : (sel == 1) ? Wk_ : (sel == 2) ? Wv_ : Wp_;
    const float* la = (sel == 0) ? laq : (sel == 1) ? lak : lav;
    const float* lb = (sel == 0) ? lbq : (sel == 1) ? lbk : lbv;
    fp16* dh = (sel < 3) ? g_Wth[sel] : g_Wpth;
    fp16* dl = (sel < 3) ? g_Wtl[sel] : g_Wptl;
    int tid = threadIdx.x, tx = tid & 31, ty = tid >> 5;
    int kb = blockIdx.y * 32, nb = blockIdx.x * 32;
    #pragma unroll
    for (int s = 0; s < 4; s++)
        ws[ty + 8 * s][tx] = W[(size_t)(kb + ty + 8 * s) * Cq + nb + tx];
    if (sel < 3) {
        for (int l = tid; l < 512; l += 256) {
            las[l >> 4][l & 15] = la[(size_t)(kb + (l >> 4)) * Rq + (l & 15)];
            lbs[l >> 5][l & 31] = lb[(size_t)(l >> 5) * Cq + nb + (l & 31)];
        }
        __syncthreads();
        float w = bw[sel];
        #pragma unroll
        for (int s = 0; s < 4; s++) {
            int i = ty + 8 * s;
            float acc = 0.f;
            #pragma unroll
            for (int r = 0; r < Rq; r++) acc = fmaf(las[i][r], lbs[r][tx], acc);
            ws[i][tx] = fmaf(w, acc, ws[i][tx]);
        }
    }
    __syncthreads();
    #pragma unroll
    for (int s = 0; s < 4; s++) {
        float v = ws[tx][ty + 8 * s];
        fp16 h, l; split_h(v, h, l);
        size_t idx = (size_t)(nb + ty + 8 * s) * Cq + kb + tx;
        dh[idx] = h; dl[idx] = l;
    }
}

// ---------------- pipelined fp16 GEMM core: 3 stages, 2 CTAs/SM ----------------
#define PITCH 40
#define NSTAGE 3
#define TILE_B 10240                       // 128*40*2
#define STAGE_B (3*TILE_B)                 // Ah, Bh, Bl
#define GEMM_DSMEM (NSTAGE*STAGE_B)        // 92160

__device__ __forceinline__ void issue_chunk(uint32_t sbase, int stage,
                                            const fp16* ah, const fp16* bh, const fp16* bl,
                                            int stride, int tid, bool twop) {
    uint32_t st = sbase + stage * STAGE_B;
    const fp16* srcs[3] = {ah, bh, bl};
    int ntiles = twop ? 3 : 2;
    for (int t = 0; t < ntiles; t++) {
        #pragma unroll
        for (int i = 0; i < 2; i++) {
            int idx = tid + 256 * i;
            int row = idx >> 2, seg = idx & 3;
            cp16(st + t * TILE_B + (row * PITCH + seg * 8) * 2,
                 srcs[t] + (size_t)row * stride + seg * 8);
        }
    }
    cp_commit();
}

__device__ __forceinline__ void compute_chunk(uint32_t sbase, int stage,
                                              float C[2][8][4], int a_off, int b_off,
                                              bool twop) {
    uint32_t st = sbase + stage * STAGE_B;
    uint32_t aH = st, bH = st + TILE_B, bL = st + 2 * TILE_B;
    #pragma unroll
    for (int kt = 0; kt < 2; kt++) {
        int ko = kt * 16;
        uint32_t ah[2][4], bh[8][2], bl[8][2];
        #pragma unroll
        for (int mt = 0; mt < 2; mt++) {
            int off = (a_off + mt * 16 * PITCH + ko) * 2;
            ldsm4(ah[mt][0], ah[mt][1], ah[mt][2], ah[mt][3], aH + off);
        }
        #pragma unroll
        for (int p = 0; p < 4; p++) {
            int off = (b_off + p * 16 * PITCH + ko) * 2;
            ldsm4(bh[2*p][0], bh[2*p][1], bh[2*p+1][0], bh[2*p+1][1], bH + off);
        }
        if (twop) {
            #pragma unroll
            for (int p = 0; p < 4; p++) {
                int off = (b_off + p * 16 * PITCH + ko) * 2;
                ldsm4(bl[2*p][0], bl[2*p][1], bl[2*p+1][0], bl[2*p+1][1], bL + off);
            }
        }
        #pragma unroll
        for (int mt = 0; mt < 2; mt++)
            #pragma unroll
            for (int nt = 0; nt < 8; nt++) {
                mma_f16(C[mt][nt], ah[mt][0], ah[mt][1], ah[mt][2], ah[mt][3],
                        bh[nt][0], bh[nt][1]);
                if (twop)
                    mma_f16(C[mt][nt], ah[mt][0], ah[mt][1], ah[mt][2], ah[mt][3],
                            bl[nt][0], bl[nt][1]);
            }
    }
}

// ---------------- qkv GEMM: all 1-pass -> q,k,v single fp16 head-split ----------------
__global__ __launch_bounds__(256, 2) void gemm_qkv_kernel() {
    extern __shared__ char dsm[];
    uint32_t sbase = smem_u32(dsm);
    int tid = threadIdx.x, lid = tid & 31, wid = tid >> 5;
    int wm = (wid & 3) * 32, wn = (wid >> 2) * 64;
    int type = blockIdx.z;
    int rowBase = blockIdx.y * 128, colBase = blockIdx.x * 128;

    const fp16* Xp = g_X16 + (size_t)rowBase * Cq;
    const fp16* Wh = g_Wth[type] + (size_t)colBase * Cq;
    const fp16* Wl = g_Wtl[type] + (size_t)colBase * Cq;

    float C[2][8][4];
    #pragma unroll
    for (int i = 0; i < 2; i++)
        #pragma unroll
        for (int j = 0; j < 8; j++)
            #pragma unroll
            for (int k = 0; k < 4; k++) C[i][j][k] = 0.f;

    int a_off = (wm + (lid & 15)) * PITCH + ((lid >> 4) & 1) * 8;
    int b_off = (wn + ((lid >> 4) & 1) * 8 + (lid & 7)) * PITCH + ((lid >> 3) & 1) * 8;

    const int NCH = 24;
    issue_chunk(sbase, 0, Xp, Wh, Wl, Cq, tid, false);
    issue_chunk(sbase, 1, Xp + 32, Wh + 32, Wl + 32, Cq, tid, false);
    for (int c = 0; c < NCH; c++) {
        cp_wait<1>();
        __syncthreads();
        int nc = c + 2;
        if (nc < NCH)
            issue_chunk(sbase, nc % 3, Xp + nc * 32, Wh + nc * 32, Wl + nc * 32, Cq, tid, false);
        else
            cp_commit();   // keep group count uniform for wait<1>
        compute_chunk(sbase, c % 3, C, a_off, b_off, false);
    }

    fp16* dst = (type == 0) ? g_q : (type == 1) ? g_k : g_v;
    float scl = (type == 0) ? QSCALE : 1.f;
    #pragma unroll
    for (int mt = 0; mt < 2; mt++)
        #pragma unroll
        for (int nt = 0; nt < 8; nt++) {
            int col = colBase + wn + nt * 8 + (lid & 3) * 2;
            int h = col >> 6, hd = col & 63;
            #pragma unroll
            for (int half = 0; half < 2; half++) {
                int row = rowBase + wm + mt * 16 + (lid >> 2) + half * 8;
                int b_ = row >> 10, n = row & 1023;
                float v0 = C[mt][nt][half * 2] * scl, v1 = C[mt][nt][half * 2 + 1] * scl;
                size_t base = (((size_t)(b_ * Hq + h) * Nq) + n) * HDq + hd;
                *(uint32_t*)&dst[base] = pkh(v0, v1);
            }
        }
}

// ---------------- output projection GEMM + bias (att single, Wp hi/lo) ----------------
__global__ __launch_bounds__(256, 2) void gemm_out_kernel(const float* __restrict__ bias,
                                                          float* __restrict__ out) {
    extern __shared__ char dsm[];
    uint32_t sbase = smem_u32(dsm);
    int tid = threadIdx.x, lid = tid & 31, wid = tid >> 5;
    int wm = (wid & 3) * 32, wn = (wid >> 2) * 64;
    int rowBase = blockIdx.y * 128, colBase = blockIdx.x * 128;

    const fp16* Ap = g_att + (size_t)rowBase * Cq;
    const fp16* Wh = g_Wpth + (size_t)colBase * Cq;
    const fp16* Wl = g_Wptl + (size_t)colBase * Cq;

    float C[2][8][4];
    #pragma unroll
    for (int i = 0; i < 2; i++)
        #pragma unroll
        for (int j = 0; j < 8; j++)
            #pragma unroll
            for (int k = 0; k < 4; k++) C[i][j][k] = 0.f;

    int a_off = (wm + (lid & 15)) * PITCH + ((lid >> 4) & 1) * 8;
    int b_off = (wn + ((lid >> 4) & 1) * 8 + (lid & 7)) * PITCH + ((lid >> 3) & 1) * 8;

    const int NCH = 24;
    issue_chunk(sbase, 0, Ap, Wh, Wl, Cq, tid, true);
    issue_chunk(sbase, 1, Ap + 32, Wh + 32, Wl + 32, Cq, tid, true);
    for (int c = 0; c < NCH; c++) {
        cp_wait<1>();
        __syncthreads();
        int nc = c + 2;
        if (nc < NCH)
            issue_chunk(sbase, nc % 3, Ap + nc * 32, Wh + nc * 32, Wl + nc * 32, Cq, tid, true);
        else
            cp_commit();
        compute_chunk(sbase, c % 3, C, a_off, b_off, true);
    }

    #pragma unroll
    for (int mt = 0; mt < 2; mt++)
        #pragma unroll
        for (int nt = 0; nt < 8; nt++) {
            int col = colBase + wn + nt * 8 + (lid & 3) * 2;
            float2 bv = *(const float2*)&bias[col];
            #pragma unroll
            for (int half = 0; half < 2; half++) {
                int row = rowBase + wm + mt * 16 + (lid >> 2) + half * 8;
                float2 v = make_float2(C[mt][nt][half * 2] + bv.x, C[mt][nt][half * 2 + 1] + bv.y);
                *(float2*)&out[(size_t)row * Cq + col] = v;
            }
        }
}

// ---------------- FA2 attention: fp16, QK 1-pass, PV 1-pass, 3-stage KV pipeline ----------
#define KVP 72
#define QBYTES (128*KVP*2)               // 18432
#define KVT (64*KVP*2)                   // 9216
#define KVSTAGE (2*KVT)                  // K, V = 18432
#define AOFF_KV QBYTES
#define ATTN_SMEM (QBYTES + 3*KVSTAGE)   // 73728

__global__ __launch_bounds__(256, 2) void attn_kernel() {
    extern __shared__ char smx[];
    uint32_t sb = smem_u32(smx);
    int tid = threadIdx.x, lid = tid & 31, wid = tid >> 5;
    int wm = wid * 16;
    int qt = blockIdx.x, head = blockIdx.y, b = blockIdx.z;
    size_t bh = (size_t)(b * Hq + head) * Nq * HDq;
    const fp16* Qg = g_q + bh + (size_t)qt * 128 * HDq;

    // stage loader: K, V for tile 'kt' into stage slot
    auto load_stage = [&](int kt, int slot) {
        uint32_t dst = sb + AOFF_KV + slot * KVSTAGE;
        const fp16* srcs[2] = {g_k + bh + (size_t)kt * 64 * HDq,
                               g_v + bh + (size_t)kt * 64 * HDq};
        #pragma unroll
        for (int t = 0; t < 2; t++)
            #pragma unroll
            for (int i = 0; i < 2; i++) {
                int idx = tid + 256 * i;
                int row = idx >> 3, seg = idx & 7;
                cp16(dst + t * KVT + (row * KVP + seg * 8) * 2,
                     srcs[t] + row * HDq + seg * 8);
            }
    };

    // prologue: Q (128 rows x 8 segs of 16B) + stage0, stage1
    #pragma unroll
    for (int i = 0; i < 4; i++) {
        int idx = tid + 256 * i;
        int row = idx >> 3, seg = idx & 7;
        cp16(sb + (row * KVP + seg * 8) * 2, Qg + row * HDq + seg * 8);
    }
    load_stage(0, 0);
    cp_commit();
    load_stage(1, 1);
    cp_commit();

    float mA = -1e30f, mB = -1e30f, lA = 0.f, lB = 0.f;
    float co[8][4];
    #pragma unroll
    for (int j = 0; j < 8; j++)
        #pragma unroll
        for (int k = 0; k < 4; k++) co[j][k] = 0.f;

    uint32_t qfrag[4][4];                 // loop-invariant Q fragments

    for (int it = 0; it < 16; it++) {
        cp_wait<1>();
        __syncthreads();
        if (it == 0) {
            #pragma unroll
            for (int ks = 0; ks < 4; ks++) {
                int offq = ((wm + (lid & 15)) * KVP + ((lid >> 4) & 1) * 8 + ks * 16) * 2;
                ldsm4(qfrag[ks][0], qfrag[ks][1], qfrag[ks][2], qfrag[ks][3], sb + offq);
            }
        }
        if (it + 2 < 16) { load_stage(it + 2, (it + 2) % 3); cp_commit(); }
        else cp_commit();

        uint32_t kv = sb + AOFF_KV + (it % 3) * KVSTAGE;
        uint32_t aK = kv, aV = kv + KVT;

        // ---- S = Q K^T : 1-pass ----
        float cs[8][4];
        #pragma unroll
        for (int j = 0; j < 8; j++)
            #pragma unroll
            for (int k = 0; k < 4; k++) cs[j][k] = 0.f;

        #pragma unroll
        for (int ks = 0; ks < 4; ks++) {
            int ko = ks * 16;
            uint32_t kh[8][2];
            #pragma unroll
            for (int p = 0; p < 4; p++) {
                int offb = ((p * 16 + ((lid >> 4) & 1) * 8 + (lid & 7)) * KVP
                            + ((lid >> 3) & 1) * 8 + ko) * 2;
                ldsm4(kh[2*p][0], kh[2*p][1], kh[2*p+1][0], kh[2*p+1][1], aK + offb);
            }
            #pragma unroll
            for (int nt = 0; nt < 8; nt++)
                mma_f16(cs[nt], qfrag[ks][0], qfrag[ks][1], qfrag[ks][2], qfrag[ks][3],
                        kh[nt][0], kh[nt][1]);
        }

        // ---- register softmax (log2 domain), deferred l-reduction ----
        float mxA = -1e30f, mxB = -1e30f;
        #pragma unroll
        for (int nt = 0; nt < 8; nt++) {
            mxA = fmaxf(mxA, fmaxf(cs[nt][0], cs[nt][1]));
            mxB = fmaxf(mxB, fmaxf(cs[nt][2], cs[nt][3]));
        }
        mxA = fmaxf(mxA, __shfl_xor_sync(0xffffffffu, mxA, 1));
        mxA = fmaxf(mxA, __shfl_xor_sync(0xffffffffu, mxA, 2));
        mxB = fmaxf(mxB, __shfl_xor_sync(0xffffffffu, mxB, 1));
        mxB = fmaxf(mxB, __shfl_xor_sync(0xffffffffu, mxB, 2));
        float mnA = fmaxf(mA, mxA), mnB = fmaxf(mB, mxB);
        float alA = ex2(mA - mnA), alB = ex2(mB - mnB);
        float psA = 0.f, psB = 0.f;
        #pragma unroll
        for (int nt = 0; nt < 8; nt++) {
            cs[nt][0] = ex2(cs[nt][0] - mnA);
            cs[nt][1] = ex2(cs[nt][1] - mnA);
            cs[nt][2] = ex2(cs[nt][2] - mnB);
            cs[nt][3] = ex2(cs[nt][3] - mnB);
            psA += cs[nt][0] + cs[nt][1];
            psB += cs[nt][2] + cs[nt][3];
        }
        lA = lA * alA + psA; mA = mnA;
        lB = lB * alB + psB; mB = mnB;

        // ---- repack P c-frags -> a-frags (fp16 single) ----
        uint32_t pa[4][4];
        #pragma unroll
        for (int ks = 0; ks < 4; ks++) {
            #pragma unroll
            for (int half = 0; half < 2; half++) {
                int nt = 2 * ks + half;
                pa[ks][2 * half]     = pkh(cs[nt][0], cs[nt][1]);
                pa[ks][2 * half + 1] = pkh(cs[nt][2], cs[nt][3]);
            }
        }

        // ---- rescale O, O += P V (1-pass) ----
        #pragma unroll
        for (int nt = 0; nt < 8; nt++) {
            co[nt][0] *= alA; co[nt][1] *= alA;
            co[nt][2] *= alB; co[nt][3] *= alB;
        }
        #pragma unroll
        for (int ks = 0; ks < 4; ks++) {
            int ko = ks * 16;
            uint32_t vh[8][2];
            #pragma unroll
            for (int dt = 0; dt < 4; dt++) {
                int offv = ((ko + (lid & 15)) * KVP + dt * 16 + ((lid >> 4) & 1) * 8) * 2;
                ldsm4t(vh[2*dt][0], vh[2*dt][1], vh[2*dt+1][0], vh[2*dt+1][1], aV + offv);
            }
            #pragma unroll
            for (int nt = 0; nt < 8; nt++)
                mma_f16(co[nt], pa[ks][0], pa[ks][1], pa[ks][2], pa[ks][3],
                        vh[nt][0], vh[nt][1]);
        }
    }

    // final l reduction across the 4 lanes sharing each row
    lA += __shfl_xor_sync(0xffffffffu, lA, 1);
    lA += __shfl_xor_sync(0xffffffffu, lA, 2);
    lB += __shfl_xor_sync(0xffffffffu, lB, 1);
    lB += __shfl_xor_sync(0xffffffffu, lB, 2);

    // epilogue: normalize, write fp16 att [B,N,C]
    float invA = 1.f / lA, invB = 1.f / lB;
    int rA = qt * 128 + wm + (lid >> 2);
    #pragma unroll
    for (int nt = 0; nt < 8; nt++) {
        int col = head * HDq + nt * 8 + (lid & 3) * 2;
        size_t base = (size_t)(b * Nq + rA) * Cq + col;
        *(uint32_t*)&g_att[base] = pkh(co[nt][0] * invA, co[nt][1] * invA);
        size_t base2 = (size_t)(b * Nq + rA + 8) * Cq + col;
        *(uint32_t*)&g_att[base2] = pkh(co[nt][2] * invB, co[nt][3] * invB);
    }
}

extern "C" void kernel_launch(void* const* d_in, const int* in_sizes, int n_in,
                              void* d_out, int out_size) {
    const float* x    = (const float*)d_in[0];
    const float* Wq   = (const float*)d_in[1];
    const float* Wk   = (const float*)d_in[2];
    const float* Wv   = (const float*)d_in[3];
    const float* Wp   = (const float*)d_in[4];
    const float* bp   = (const float*)d_in[5];
    const float* la_q = (const float*)d_in[6];
    const float* lb_q = (const float*)d_in[7];
    const float* la_k = (const float*)d_in[8];
    const float* lb_k = (const float*)d_in[9];
    const float* la_v = (const float*)d_in[10];
    const float* lb_v = (const float*)d_in[11];
    const float* bw   = (const float*)d_in[12];
    float* out = (float*)d_out;

    convert_x_kernel<<<(ROWS * Cq + 255) / 256, 256>>>(x);
    wprime_kernel<<<dim3(24, 24, 4), 256>>>(Wq, Wk, Wv, Wp,
                                            la_q, lb_q, la_k, lb_k, la_v, lb_v, bw);

    cudaFuncSetAttribute(gemm_qkv_kernel, cudaFuncAttributeMaxDynamicSharedMemorySize, GEMM_DSMEM);
    gemm_qkv_kernel<<<dim3(6, 64, 3), 256, GEMM_DSMEM>>>();

    cudaFuncSetAttribute(attn_kernel, cudaFuncAttributeMaxDynamicSharedMemorySize, ATTN_SMEM);
    attn_kernel<<<dim3(Nq / 128, Hq, Bq), 256, ATTN_SMEM>>>();

    cudaFuncSetAttribute(gemm_out_kernel, cudaFuncAttributeMaxDynamicSharedMemorySize, GEMM_DSMEM);
    gemm_out_kernel<<<dim3(6, 64), 256, GEMM_DSMEM>>>(bp, out);
}

// round 14
// speedup vs baseline: 2.3392x; 1.1090x over previous
#include <cuda_runtime.h>
#include <cuda_fp16.h>
#include <cstdint>

#define Bq 8
#define Nq 1024
#define Cq 768
#define Hq 12
#define HDq 64
#define Rq 16
#define ROWS (Bq*Nq)
#define QSCALE 0.18033688011112042f   // 0.125 * log2(e)

typedef __half fp16;

// ---------------- helpers ----------------
__device__ __forceinline__ uint32_t smem_u32(const void* p) {
    uint32_t a;
    asm("{ .reg .u64 t; cvta.to.shared.u64 t, %1; cvt.u32.u64 %0, t; }" : "=r"(a) : "l"(p));
    return a;
}
__device__ __forceinline__ void ldsm4(uint32_t& r0, uint32_t& r1, uint32_t& r2, uint32_t& r3,
                                      uint32_t addr) {
    asm volatile("ldmatrix.sync.aligned.m8n8.x4.shared.b16 {%0,%1,%2,%3}, [%4];"
                 : "=r"(r0), "=r"(r1), "=r"(r2), "=r"(r3) : "r"(addr));
}
__device__ __forceinline__ void ldsm4t(uint32_t& r0, uint32_t& r1, uint32_t& r2, uint32_t& r3,
                                       uint32_t addr) {
    asm volatile("ldmatrix.sync.aligned.m8n8.x4.trans.shared.b16 {%0,%1,%2,%3}, [%4];"
                 : "=r"(r0), "=r"(r1), "=r"(r2), "=r"(r3) : "r"(addr));
}
__device__ __forceinline__ void mma_f16(float* c, uint32_t a0, uint32_t a1, uint32_t a2,
                                        uint32_t a3, uint32_t b0, uint32_t b1) {
    asm("mma.sync.aligned.m16n8k16.row.col.f32.f16.f16.f32 "
        "{%0,%1,%2,%3}, {%4,%5,%6,%7}, {%8,%9}, {%0,%1,%2,%3};"
        : "+f"(c[0]), "+f"(c[1]), "+f"(c[2]), "+f"(c[3])
        : "r"(a0), "r"(a1), "r"(a2), "r"(a3), "r"(b0), "r"(b1));
}
__device__ __forceinline__ void cp16(uint32_t dst, const void* src) {
    asm volatile("cp.async.cg.shared.global [%0], [%1], 16;" :: "r"(dst), "l"(src));
}
__device__ __forceinline__ void cp_commit() {
    asm volatile("cp.async.commit_group;" ::: "memory");
}
template <int N>
__device__ __forceinline__ void cp_wait() {
    asm volatile("cp.async.wait_group %0;" :: "n"(N) : "memory");
}
__device__ __forceinline__ float ex2(float x) {
    float y; asm("ex2.approx.f32 %0, %1;" : "=f"(y) : "f"(x)); return y;
}
__device__ __forceinline__ uint32_t pkh(float a, float b) {
    __half2 t = __floats2half2_rn(a, b);
    return *(uint32_t*)&t;
}

// ---------------- scratch ----------------
__device__ fp16 g_q[Bq*Hq*Nq*HDq];                    // single, pre-scaled by QSCALE
__device__ fp16 g_k[Bq*Hq*Nq*HDq];
__device__ fp16 g_v[Bq*Hq*Nq*HDq];
__device__ fp16 g_X16[ROWS*Cq];
__device__ fp16 g_Wt[3][Cq*Cq];                       // (W + bw*la@lb)^T fp16
__device__ fp16 g_Wpt[Cq*Cq];
__device__ fp16 g_att[ROWS*Cq];

// ---------------- prep kernels ----------------
__global__ void convert_x_kernel(const float* __restrict__ X) {
    int i = blockIdx.x * blockDim.x + threadIdx.x;
    if (i < ROWS * Cq) g_X16[i] = __float2half_rn(X[i]);
}

// W' = W + bw*(la@lb)  (sel<3), or plain Wp (sel=3); write transposed fp16
__global__ __launch_bounds__(256) void wprime_kernel(
        const float* __restrict__ Wq_, const float* __restrict__ Wk_,
        const float* __restrict__ Wv_, const float* __restrict__ Wp_,
        const float* __restrict__ laq, const float* __restrict__ lbq,
        const float* __restrict__ lak, const float* __restrict__ lbk,
        const float* __restrict__ lav, const float* __restrict__ lbv,
        const float* __restrict__ bw) {
    __shared__ float ws[32][33];
    __shared__ float las[32][16];
    __shared__ float lbs[16][33];
    int sel = blockIdx.z;
    const float* W  = (sel == 0) ? Wq_ : (sel == 1) ? Wk_ : (sel == 2) ? Wv_ : Wp_;
    const float* la = (sel == 0) ? laq : (sel == 1) ? lak : lav;
    const float* lb = (sel == 0) ? lbq : (sel == 1) ? lbk : lbv;
    fp16* dh = (sel < 3) ? g_Wt[sel] : g_Wpt;
    int tid = threadIdx.x, tx = tid & 31, ty = tid >> 5;
    int kb = blockIdx.y * 32, nb = blockIdx.x * 32;
    #pragma unroll
    for (int s = 0; s < 4; s++)
        ws[ty + 8 * s][tx] = W[(size_t)(kb + ty + 8 * s) * Cq + nb + tx];
    if (sel < 3) {
        for (int l = tid; l < 512; l += 256) {
            las[l >> 4][l & 15] = la[(size_t)(kb + (l >> 4)) * Rq + (l & 15)];
            lbs[l >> 5][l & 31] = lb[(size_t)(l >> 5) * Cq + nb + (l & 31)];
        }
        __syncthreads();
        float w = bw[sel];
        #pragma unroll
        for (int s = 0; s < 4; s++) {
            int i = ty + 8 * s;
            float acc = 0.f;
            #pragma unroll
            for (int r = 0; r < Rq; r++) acc = fmaf(las[i][r], lbs[r][tx], acc);
            ws[i][tx] = fmaf(w, acc, ws[i][tx]);
        }
    }
    __syncthreads();
    #pragma unroll
    for (int s = 0; s < 4; s++) {
        float v = ws[tx][ty + 8 * s];
        dh[(size_t)(nb + ty + 8 * s) * Cq + kb + tx] = __float2half_rn(v);
    }
}

// ---------------- pipelined fp16 GEMM core: 1-pass, 3 stages, 2 CTAs/SM ----------------
#define PITCH 40
#define TILE_B 10240                       // 128*40*2
#define STAGE_B (2*TILE_B)                 // A, B
#define GEMM_DSMEM (3*STAGE_B)             // 61440

__device__ __forceinline__ void issue_chunk(uint32_t sbase, int stage,
                                            const fp16* a, const fp16* b,
                                            int stride, int tid) {
    uint32_t st = sbase + stage * STAGE_B;
    const fp16* srcs[2] = {a, b};
    #pragma unroll
    for (int t = 0; t < 2; t++) {
        #pragma unroll
        for (int i = 0; i < 2; i++) {
            int idx = tid + 256 * i;
            int row = idx >> 2, seg = idx & 3;
            cp16(st + t * TILE_B + (row * PITCH + seg * 8) * 2,
                 srcs[t] + (size_t)row * stride + seg * 8);
        }
    }
    cp_commit();
}

__device__ __forceinline__ void compute_chunk(uint32_t sbase, int stage,
                                              float C[2][8][4], int a_off, int b_off) {
    uint32_t st = sbase + stage * STAGE_B;
    uint32_t aB = st, bB = st + TILE_B;
    #pragma unroll
    for (int kt = 0; kt < 2; kt++) {
        int ko = kt * 16;
        uint32_t ah[2][4], bh[8][2];
        #pragma unroll
        for (int mt = 0; mt < 2; mt++) {
            int off = (a_off + mt * 16 * PITCH + ko) * 2;
            ldsm4(ah[mt][0], ah[mt][1], ah[mt][2], ah[mt][3], aB + off);
        }
        #pragma unroll
        for (int p = 0; p < 4; p++) {
            int off = (b_off + p * 16 * PITCH + ko) * 2;
            ldsm4(bh[2*p][0], bh[2*p][1], bh[2*p+1][0], bh[2*p+1][1], bB + off);
        }
        #pragma unroll
        for (int mt = 0; mt < 2; mt++)
            #pragma unroll
            for (int nt = 0; nt < 8; nt++)
                mma_f16(C[mt][nt], ah[mt][0], ah[mt][1], ah[mt][2], ah[mt][3],
                        bh[nt][0], bh[nt][1]);
    }
}

// ---------------- qkv GEMM: 1-pass -> q,k,v single fp16 head-split ----------------
__global__ __launch_bounds__(256, 2) void gemm_qkv_kernel() {
    extern __shared__ char dsm[];
    uint32_t sbase = smem_u32(dsm);
    int tid = threadIdx.x, lid = tid & 31, wid = tid >> 5;
    int wm = (wid & 3) * 32, wn = (wid >> 2) * 64;
    int type = blockIdx.z;
    int rowBase = blockIdx.y * 128, colBase = blockIdx.x * 128;

    const fp16* Xp = g_X16 + (size_t)rowBase * Cq;
    const fp16* Wp = g_Wt[type] + (size_t)colBase * Cq;

    float C[2][8][4];
    #pragma unroll
    for (int i = 0; i < 2; i++)
        #pragma unroll
        for (int j = 0; j < 8; j++)
            #pragma unroll
            for (int k = 0; k < 4; k++) C[i][j][k] = 0.f;

    int a_off = (wm + (lid & 15)) * PITCH + ((lid >> 4) & 1) * 8;
    int b_off = (wn + ((lid >> 4) & 1) * 8 + (lid & 7)) * PITCH + ((lid >> 3) & 1) * 8;

    const int NCH = 24;
    issue_chunk(sbase, 0, Xp, Wp, Cq, tid);
    issue_chunk(sbase, 1, Xp + 32, Wp + 32, Cq, tid);
    for (int c = 0; c < NCH; c++) {
        cp_wait<1>();
        __syncthreads();
        int nc = c + 2;
        if (nc < NCH)
            issue_chunk(sbase, nc % 3, Xp + nc * 32, Wp + nc * 32, Cq, tid);
        else
            cp_commit();
        compute_chunk(sbase, c % 3, C, a_off, b_off);
    }

    fp16* dst = (type == 0) ? g_q : (type == 1) ? g_k : g_v;
    float scl = (type == 0) ? QSCALE : 1.f;
    #pragma unroll
    for (int mt = 0; mt < 2; mt++)
        #pragma unroll
        for (int nt = 0; nt < 8; nt++) {
            int col = colBase + wn + nt * 8 + (lid & 3) * 2;
            int h = col >> 6, hd = col & 63;
            #pragma unroll
            for (int half = 0; half < 2; half++) {
                int row = rowBase + wm + mt * 16 + (lid >> 2) + half * 8;
                int b_ = row >> 10, n = row & 1023;
                float v0 = C[mt][nt][half * 2] * scl, v1 = C[mt][nt][half * 2 + 1] * scl;
                size_t base = (((size_t)(b_ * Hq + h) * Nq) + n) * HDq + hd;
                *(uint32_t*)&dst[base] = pkh(v0, v1);
            }
        }
}

// ---------------- output projection GEMM + bias (1-pass) ----------------
__global__ __launch_bounds__(256, 2) void gemm_out_kernel(const float* __restrict__ bias,
                                                          float* __restrict__ out) {
    extern __shared__ char dsm[];
    uint32_t sbase = smem_u32(dsm);
    int tid = threadIdx.x, lid = tid & 31, wid = tid >> 5;
    int wm = (wid & 3) * 32, wn = (wid >> 2) * 64;
    int rowBase = blockIdx.y * 128, colBase = blockIdx.x * 128;

    const fp16* Ap = g_att + (size_t)rowBase * Cq;
    const fp16* Wp = g_Wpt + (size_t)colBase * Cq;

    float C[2][8][4];
    #pragma unroll
    for (int i = 0; i < 2; i++)
        #pragma unroll
        for (int j = 0; j < 8; j++)
            #pragma unroll
            for (int k = 0; k < 4; k++) C[i][j][k] = 0.f;

    int a_off = (wm + (lid & 15)) * PITCH + ((lid >> 4) & 1) * 8;
    int b_off = (wn + ((lid >> 4) & 1) * 8 + (lid & 7)) * PITCH + ((lid >> 3) & 1) * 8;

    const int NCH = 24;
    issue_chunk(sbase, 0, Ap, Wp, Cq, tid);
    issue_chunk(sbase, 1, Ap + 32, Wp + 32, Cq, tid);
    for (int c = 0; c < NCH; c++) {
        cp_wait<1>();
        __syncthreads();
        int nc = c + 2;
        if (nc < NCH)
            issue_chunk(sbase, nc % 3, Ap + nc * 32, Wp + nc * 32, Cq, tid);
        else
            cp_commit();
        compute_chunk(sbase, c % 3, C, a_off, b_off);
    }

    #pragma unroll
    for (int mt = 0; mt < 2; mt++)
        #pragma unroll
        for (int nt = 0; nt < 8; nt++) {
            int col = colBase + wn + nt * 8 + (lid & 3) * 2;
            float2 bv = *(const float2*)&bias[col];
            #pragma unroll
            for (int half = 0; half < 2; half++) {
                int row = rowBase + wm + mt * 16 + (lid >> 2) + half * 8;
                float2 v = make_float2(C[mt][nt][half * 2] + bv.x, C[mt][nt][half * 2 + 1] + bv.y);
                *(float2*)&out[(size_t)row * Cq + col] = v;
            }
        }
}

// ---------------- FA2 attention: fp16 single, 3-stage KV pipeline ----------
#define KVP 72
#define QBYTES (128*KVP*2)               // 18432
#define KVT (64*KVP*2)                   // 9216
#define KVSTAGE (2*KVT)                  // K, V
#define AOFF_KV QBYTES
#define ATTN_SMEM (QBYTES + 3*KVSTAGE)   // 73728

__global__ __launch_bounds__(256, 2) void attn_kernel() {
    extern __shared__ char smx[];
    uint32_t sb = smem_u32(smx);
    int tid = threadIdx.x, lid = tid & 31, wid = tid >> 5;
    int wm = wid * 16;
    int qt = blockIdx.x, head = blockIdx.y, b = blockIdx.z;
    size_t bh = (size_t)(b * Hq + head) * Nq * HDq;
    const fp16* Qg = g_q + bh + (size_t)qt * 128 * HDq;

    auto load_stage = [&](int kt, int slot) {
        uint32_t dst = sb + AOFF_KV + slot * KVSTAGE;
        const fp16* srcs[2] = {g_k + bh + (size_t)kt * 64 * HDq,
                               g_v + bh + (size_t)kt * 64 * HDq};
        #pragma unroll
        for (int t = 0; t < 2; t++)
            #pragma unroll
            for (int i = 0; i < 2; i++) {
                int idx = tid + 256 * i;
                int row = idx >> 3, seg = idx & 7;
                cp16(dst + t * KVT + (row * KVP + seg * 8) * 2,
                     srcs[t] + row * HDq + seg * 8);
            }
    };

    #pragma unroll
    for (int i = 0; i < 4; i++) {
        int idx = tid + 256 * i;
        int row = idx >> 3, seg = idx & 7;
        cp16(sb + (row * KVP + seg * 8) * 2, Qg + row * HDq + seg * 8);
    }
    load_stage(0, 0);
    cp_commit();
    load_stage(1, 1);
    cp_commit();

    float mA = -1e30f, mB = -1e30f, lA = 0.f, lB = 0.f;
    float co[8][4];
    #pragma unroll
    for (int j = 0; j < 8; j++)
        #pragma unroll
        for (int k = 0; k < 4; k++) co[j][k] = 0.f;

    uint32_t qfrag[4][4];

    for (int it = 0; it < 16; it++) {
        cp_wait<1>();
        __syncthreads();
        if (it == 0) {
            #pragma unroll
            for (int ks = 0; ks < 4; ks++) {
                int offq = ((wm + (lid & 15)) * KVP + ((lid >> 4) & 1) * 8 + ks * 16) * 2;
                ldsm4(qfrag[ks][0], qfrag[ks][1], qfrag[ks][2], qfrag[ks][3], sb + offq);
            }
        }
        if (it + 2 < 16) { load_stage(it + 2, (it + 2) % 3); cp_commit(); }
        else cp_commit();

        uint32_t kv = sb + AOFF_KV + (it % 3) * KVSTAGE;
        uint32_t aK = kv, aV = kv + KVT;

        float cs[8][4];
        #pragma unroll
        for (int j = 0; j < 8; j++)
            #pragma unroll
            for (int k = 0; k < 4; k++) cs[j][k] = 0.f;

        #pragma unroll
        for (int ks = 0; ks < 4; ks++) {
            int ko = ks * 16;
            uint32_t kh[8][2];
            #pragma unroll
            for (int p = 0; p < 4; p++) {
                int offb = ((p * 16 + ((lid >> 4) & 1) * 8 + (lid & 7)) * KVP
                            + ((lid >> 3) & 1) * 8 + ko) * 2;
                ldsm4(kh[2*p][0], kh[2*p][1], kh[2*p+1][0], kh[2*p+1][1], aK + offb);
            }
            #pragma unroll
            for (int nt = 0; nt < 8; nt++)
                mma_f16(cs[nt], qfrag[ks][0], qfrag[ks][1], qfrag[ks][2], qfrag[ks][3],
                        kh[nt][0], kh[nt][1]);
        }

        float mxA = -1e30f, mxB = -1e30f;
        #pragma unroll
        for (int nt = 0; nt < 8; nt++) {
            mxA = fmaxf(mxA, fmaxf(cs[nt][0], cs[nt][1]));
            mxB = fmaxf(mxB, fmaxf(cs[nt][2], cs[nt][3]));
        }
        mxA = fmaxf(mxA, __shfl_xor_sync(0xffffffffu, mxA, 1));
        mxA = fmaxf(mxA, __shfl_xor_sync(0xffffffffu, mxA, 2));
        mxB = fmaxf(mxB, __shfl_xor_sync(0xffffffffu, mxB, 1));
        mxB = fmaxf(mxB, __shfl_xor_sync(0xffffffffu, mxB, 2));
        float mnA = fmaxf(mA, mxA), mnB = fmaxf(mB, mxB);
        float alA = ex2(mA - mnA), alB = ex2(mB - mnB);
        float psA = 0.f, psB = 0.f;
        #pragma unroll
        for (int nt = 0; nt < 8; nt++) {
            cs[nt][0] = ex2(cs[nt][0] - mnA);
            cs[nt][1] = ex2(cs[nt][1] - mnA);
            cs[nt][2] = ex2(cs[nt][2] - mnB);
            cs[nt][3] = ex2(cs[nt][3] - mnB);
            psA += cs[nt][0] + cs[nt][1];
            psB += cs[nt][2] + cs[nt][3];
        }
        lA = lA * alA + psA; mA = mnA;
        lB = lB * alB + psB; mB = mnB;

        uint32_t pa[4][4];
        #pragma unroll
        for (int ks = 0; ks < 4; ks++) {
            #pragma unroll
            for (int half = 0; half < 2; half++) {
                int nt = 2 * ks + half;
                pa[ks][2 * half]     = pkh(cs[nt][0], cs[nt][1]);
                pa[ks][2 * half + 1] = pkh(cs[nt][2], cs[nt][3]);
            }
        }

        #pragma unroll
        for (int nt = 0; nt < 8; nt++) {
            co[nt][0] *= alA; co[nt][1] *= alA;
            co[nt][2] *= alB; co[nt][3] *= alB;
        }
        #pragma unroll
        for (int ks = 0; ks < 4; ks++) {
            int ko = ks * 16;
            uint32_t vh[8][2];
            #pragma unroll
            for (int dt = 0; dt < 4; dt++) {
                int offv = ((ko + (lid & 15)) * KVP + dt * 16 + ((lid >> 4) & 1) * 8) * 2;
                ldsm4t(vh[2*dt][0], vh[2*dt][1], vh[2*dt+1][0], vh[2*dt+1][1], aV + offv);
            }
            #pragma unroll
            for (int nt = 0; nt < 8; nt++)
                mma_f16(co[nt], pa[ks][0], pa[ks][1], pa[ks][2], pa[ks][3],
                        vh[nt][0], vh[nt][1]);
        }
    }

    lA += __shfl_xor_sync(0xffffffffu, lA, 1);
    lA += __shfl_xor_sync(0xffffffffu, lA, 2);
    lB += __shfl_xor_sync(0xffffffffu, lB, 1);
    lB += __shfl_xor_sync(0xffffffffu, lB, 2);

    float invA = 1.f / lA, invB = 1.f / lB;
    int rA = qt * 128 + wm + (lid >> 2);
    #pragma unroll
    for (int nt = 0; nt < 8; nt++) {
        int col = head * HDq + nt * 8 + (lid & 3) * 2;
        size_t base = (size_t)(b * Nq + rA) * Cq + col;
        *(uint32_t*)&g_att[base] = pkh(co[nt][0] * invA, co[nt][1] * invA);
        size_t base2 = (size_t)(b * Nq + rA + 8) * Cq + col;
        *(uint32_t*)&g_att[base2] = pkh(co[nt][2] * invB, co[nt][3] * invB);
    }
}

extern "C" void kernel_launch(void* const* d_in, const int* in_sizes, int n_in,
                              void* d_out, int out_size) {
    const float* x    = (const float*)d_in[0];
    const float* Wq   = (const float*)d_in[1];
    const float* Wk   = (const float*)d_in[2];
    const float* Wv   = (const float*)d_in[3];
    const float* Wp   = (const float*)d_in[4];
    const float* bp   = (const float*)d_in[5];
    const float* la_q = (const float*)d_in[6];
    const float* lb_q = (const float*)d_in[7];
    const float* la_k = (const float*)d_in[8];
    const float* lb_k = (const float*)d_in[9];
    const float* la_v = (const float*)d_in[10];
    const float* lb_v = (const float*)d_in[11];
    const float* bw   = (const float*)d_in[12];
    float* out = (float*)d_out;

    convert_x_kernel<<<(ROWS * Cq + 255) / 256, 256>>>(x);
    wprime_kernel<<<dim3(24, 24, 4), 256>>>(Wq, Wk, Wv, Wp,
                                            la_q, lb_q, la_k, lb_k, la_v, lb_v, bw);

    cudaFuncSetAttribute(gemm_qkv_kernel, cudaFuncAttributeMaxDynamicSharedMemorySize, GEMM_DSMEM);
    gemm_qkv_kernel<<<dim3(6, 64, 3), 256, GEMM_DSMEM>>>();

    cudaFuncSetAttribute(attn_kernel, cudaFuncAttributeMaxDynamicSharedMemorySize, ATTN_SMEM);
    attn_kernel<<<dim3(Nq / 128, Hq, Bq), 256, ATTN_SMEM>>>();

    cudaFuncSetAttribute(gemm_out_kernel, cudaFuncAttributeMaxDynamicSharedMemorySize, GEMM_DSMEM);
    gemm_out_kernel<<<dim3(6, 64), 256, GEMM_DSMEM>>>(bp, out);
}

// round 15
// speedup vs baseline: 2.4717x; 1.0566x over previous
#include <cuda_runtime.h>
#include <cuda_fp16.h>
#include <cstdint>

#define Bq 8
#define Nq 1024
#define Cq 768
#define Hq 12
#define HDq 64
#define Rq 16
#define ROWS (Bq*Nq)
#define QSCALE 0.18033688011112042f   // 0.125 * log2(e)

typedef __half fp16;

// ---------------- helpers ----------------
__device__ __forceinline__ uint32_t smem_u32(const void* p) {
    uint32_t a;
    asm("{ .reg .u64 t; cvta.to.shared.u64 t, %1; cvt.u32.u64 %0, t; }" : "=r"(a) : "l"(p));
    return a;
}
__device__ __forceinline__ void ldsm4(uint32_t& r0, uint32_t& r1, uint32_t& r2, uint32_t& r3,
                                      uint32_t addr) {
    asm volatile("ldmatrix.sync.aligned.m8n8.x4.shared.b16 {%0,%1,%2,%3}, [%4];"
                 : "=r"(r0), "=r"(r1), "=r"(r2), "=r"(r3) : "r"(addr));
}
__device__ __forceinline__ void ldsm4t(uint32_t& r0, uint32_t& r1, uint32_t& r2, uint32_t& r3,
                                       uint32_t addr) {
    asm volatile("ldmatrix.sync.aligned.m8n8.x4.trans.shared.b16 {%0,%1,%2,%3}, [%4];"
                 : "=r"(r0), "=r"(r1), "=r"(r2), "=r"(r3) : "r"(addr));
}
__device__ __forceinline__ void mma_f16(float* c, uint32_t a0, uint32_t a1, uint32_t a2,
                                        uint32_t a3, uint32_t b0, uint32_t b1) {
    asm("mma.sync.aligned.m16n8k16.row.col.f32.f16.f16.f32 "
        "{%0,%1,%2,%3}, {%4,%5,%6,%7}, {%8,%9}, {%0,%1,%2,%3};"
        : "+f"(c[0]), "+f"(c[1]), "+f"(c[2]), "+f"(c[3])
        : "r"(a0), "r"(a1), "r"(a2), "r"(a3), "r"(b0), "r"(b1));
}
__device__ __forceinline__ void cp16(uint32_t dst, const void* src) {
    asm volatile("cp.async.cg.shared.global [%0], [%1], 16;" :: "r"(dst), "l"(src));
}
__device__ __forceinline__ void cp_commit() {
    asm volatile("cp.async.commit_group;" ::: "memory");
}
template <int N>
__device__ __forceinline__ void cp_wait() {
    asm volatile("cp.async.wait_group %0;" :: "n"(N) : "memory");
}
__device__ __forceinline__ float ex2(float x) {
    float y; asm("ex2.approx.f32 %0, %1;" : "=f"(y) : "f"(x)); return y;
}
__device__ __forceinline__ uint32_t pkh(float a, float b) {
    __half2 t = __floats2half2_rn(a, b);
    return *(uint32_t*)&t;
}

// ---------------- scratch ----------------
__device__ fp16 g_q[Bq*Hq*Nq*HDq];                    // single, pre-scaled by QSCALE
__device__ fp16 g_k[Bq*Hq*Nq*HDq];
__device__ fp16 g_v[Bq*Hq*Nq*HDq];
__device__ fp16 g_X16[ROWS*Cq];
__device__ fp16 g_Wt[3][Cq*Cq];                       // (W + bw*la@lb)^T fp16
__device__ fp16 g_Wpt[Cq*Cq];
__device__ fp16 g_att[ROWS*Cq];

// ---------------- prep kernels ----------------
__global__ void convert_x_kernel(const float* __restrict__ X) {
    int i = blockIdx.x * blockDim.x + threadIdx.x;   // one float4 per thread
    if (i < ROWS * Cq / 4) {
        float4 v = ((const float4*)X)[i];
        uint32_t lo = pkh(v.x, v.y), hi = pkh(v.z, v.w);
        ((uint2*)g_X16)[i] = make_uint2(lo, hi);
    }
}

// W' = W + bw*(la@lb)  (sel<3), or plain Wp (sel=3); write transposed fp16
__global__ __launch_bounds__(256) void wprime_kernel(
        const float* __restrict__ Wq_, const float* __restrict__ Wk_,
        const float* __restrict__ Wv_, const float* __restrict__ Wp_,
        const float* __restrict__ laq, const float* __restrict__ lbq,
        const float* __restrict__ lak, const float* __restrict__ lbk,
        const float* __restrict__ lav, const float* __restrict__ lbv,
        const float* __restrict__ bw) {
    __shared__ float ws[32][33];
    __shared__ float las[32][16];
    __shared__ float lbs[16][33];
    int sel = blockIdx.z;
    const float* W  = (sel == 0) ? Wq_ : (sel == 1) ? Wk_ : (sel == 2) ? Wv_ : Wp_;
    const float* la = (sel == 0) ? laq : (sel == 1) ? lak : lav;
    const float* lb = (sel == 0) ? lbq : (sel == 1) ? lbk : lbv;
    fp16* dh = (sel < 3) ? g_Wt[sel] : g_Wpt;
    int tid = threadIdx.x, tx = tid & 31, ty = tid >> 5;
    int kb = blockIdx.y * 32, nb = blockIdx.x * 32;
    #pragma unroll
    for (int s = 0; s < 4; s++)
        ws[ty + 8 * s][tx] = W[(size_t)(kb + ty + 8 * s) * Cq + nb + tx];
    if (sel < 3) {
        for (int l = tid; l < 512; l += 256) {
            las[l >> 4][l & 15] = la[(size_t)(kb + (l >> 4)) * Rq + (l & 15)];
            lbs[l >> 5][l & 31] = lb[(size_t)(l >> 5) * Cq + nb + (l & 31)];
        }
        __syncthreads();
        float w = bw[sel];
        #pragma unroll
        for (int s = 0; s < 4; s++) {
            int i = ty + 8 * s;
            float acc = 0.f;
            #pragma unroll
            for (int r = 0; r < Rq; r++) acc = fmaf(las[i][r], lbs[r][tx], acc);
            ws[i][tx] = fmaf(w, acc, ws[i][tx]);
        }
    }
    __syncthreads();
    #pragma unroll
    for (int s = 0; s < 4; s++) {
        float v = ws[tx][ty + 8 * s];
        dh[(size_t)(nb + ty + 8 * s) * Cq + kb + tx] = __float2half_rn(v);
    }
}

// ---------------- pipelined fp16 GEMM core: K-chunk 64, 2 stages, 2 CTAs/SM ----------------
#define GP 72                              // pitch (elements) for 64-wide rows
#define GTILE_B (128*GP*2)                 // 18432
#define GSTAGE_B (2*GTILE_B)               // A, B = 36864
#define GEMM_DSMEM (2*GSTAGE_B)            // 73728

__device__ __forceinline__ void issue_chunk(uint32_t sbase, int stage,
                                            const fp16* a, const fp16* b,
                                            int stride, int tid) {
    uint32_t st = sbase + stage * GSTAGE_B;
    const fp16* srcs[2] = {a, b};
    #pragma unroll
    for (int t = 0; t < 2; t++) {
        #pragma unroll
        for (int i = 0; i < 4; i++) {
            int idx = tid + 256 * i;           // 1024 = 128 rows x 8 segs
            int row = idx >> 3, seg = idx & 7;
            cp16(st + t * GTILE_B + (row * GP + seg * 8) * 2,
                 srcs[t] + (size_t)row * stride + seg * 8);
        }
    }
    cp_commit();
}

__device__ __forceinline__ void compute_chunk(uint32_t sbase, int stage,
                                              float C[2][8][4], int a_off, int b_off) {
    uint32_t st = sbase + stage * GSTAGE_B;
    uint32_t aB = st, bB = st + GTILE_B;
    #pragma unroll
    for (int kt = 0; kt < 4; kt++) {
        int ko = kt * 16;
        uint32_t ah[2][4], bh[8][2];
        #pragma unroll
        for (int mt = 0; mt < 2; mt++) {
            int off = (a_off + mt * 16 * GP + ko) * 2;
            ldsm4(ah[mt][0], ah[mt][1], ah[mt][2], ah[mt][3], aB + off);
        }
        #pragma unroll
        for (int p = 0; p < 4; p++) {
            int off = (b_off + p * 16 * GP + ko) * 2;
            ldsm4(bh[2*p][0], bh[2*p][1], bh[2*p+1][0], bh[2*p+1][1], bB + off);
        }
        #pragma unroll
        for (int mt = 0; mt < 2; mt++)
            #pragma unroll
            for (int nt = 0; nt < 8; nt++)
                mma_f16(C[mt][nt], ah[mt][0], ah[mt][1], ah[mt][2], ah[mt][3],
                        bh[nt][0], bh[nt][1]);
    }
}

// ---------------- qkv GEMM: 1-pass -> q,k,v single fp16 head-split ----------------
__global__ __launch_bounds__(256, 2) void gemm_qkv_kernel() {
    extern __shared__ char dsm[];
    uint32_t sbase = smem_u32(dsm);
    int tid = threadIdx.x, lid = tid & 31, wid = tid >> 5;
    int wm = (wid & 3) * 32, wn = (wid >> 2) * 64;
    int type = blockIdx.z;
    int rowBase = blockIdx.y * 128, colBase = blockIdx.x * 128;

    const fp16* Xp = g_X16 + (size_t)rowBase * Cq;
    const fp16* Wp = g_Wt[type] + (size_t)colBase * Cq;

    float C[2][8][4];
    #pragma unroll
    for (int i = 0; i < 2; i++)
        #pragma unroll
        for (int j = 0; j < 8; j++)
            #pragma unroll
            for (int k = 0; k < 4; k++) C[i][j][k] = 0.f;

    int a_off = (wm + (lid & 15)) * GP + ((lid >> 4) & 1) * 8;
    int b_off = (wn + ((lid >> 4) & 1) * 8 + (lid & 7)) * GP + ((lid >> 3) & 1) * 8;

    const int NCH = 12;                     // 12 chunks of K=64
    issue_chunk(sbase, 0, Xp, Wp, Cq, tid);
    for (int c = 0; c < NCH; c++) {
        cp_wait<0>();
        __syncthreads();
        int nc = c + 1;
        if (nc < NCH)
            issue_chunk(sbase, nc & 1, Xp + nc * 64, Wp + nc * 64, Cq, tid);
        compute_chunk(sbase, c & 1, C, a_off, b_off);
    }

    fp16* dst = (type == 0) ? g_q : (type == 1) ? g_k : g_v;
    float scl = (type == 0) ? QSCALE : 1.f;
    #pragma unroll
    for (int mt = 0; mt < 2; mt++)
        #pragma unroll
        for (int nt = 0; nt < 8; nt++) {
            int col = colBase + wn + nt * 8 + (lid & 3) * 2;
            int h = col >> 6, hd = col & 63;
            #pragma unroll
            for (int half = 0; half < 2; half++) {
                int row = rowBase + wm + mt * 16 + (lid >> 2) + half * 8;
                int b_ = row >> 10, n = row & 1023;
                float v0 = C[mt][nt][half * 2] * scl, v1 = C[mt][nt][half * 2 + 1] * scl;
                size_t base = (((size_t)(b_ * Hq + h) * Nq) + n) * HDq + hd;
                *(uint32_t*)&dst[base] = pkh(v0, v1);
            }
        }
}

// ---------------- output projection GEMM + bias (1-pass) ----------------
__global__ __launch_bounds__(256, 2) void gemm_out_kernel(const float* __restrict__ bias,
                                                          float* __restrict__ out) {
    extern __shared__ char dsm[];
    uint32_t sbase = smem_u32(dsm);
    int tid = threadIdx.x, lid = tid & 31, wid = tid >> 5;
    int wm = (wid & 3) * 32, wn = (wid >> 2) * 64;
    int rowBase = blockIdx.y * 128, colBase = blockIdx.x * 128;

    const fp16* Ap = g_att + (size_t)rowBase * Cq;
    const fp16* Wp = g_Wpt + (size_t)colBase * Cq;

    float C[2][8][4];
    #pragma unroll
    for (int i = 0; i < 2; i++)
        #pragma unroll
        for (int j = 0; j < 8; j++)
            #pragma unroll
            for (int k = 0; k < 4; k++) C[i][j][k] = 0.f;

    int a_off = (wm + (lid & 15)) * GP + ((lid >> 4) & 1) * 8;
    int b_off = (wn + ((lid >> 4) & 1) * 8 + (lid & 7)) * GP + ((lid >> 3) & 1) * 8;

    const int NCH = 12;
    issue_chunk(sbase, 0, Ap, Wp, Cq, tid);
    for (int c = 0; c < NCH; c++) {
        cp_wait<0>();
        __syncthreads();
        int nc = c + 1;
        if (nc < NCH)
            issue_chunk(sbase, nc & 1, Ap + nc * 64, Wp + nc * 64, Cq, tid);
        compute_chunk(sbase, c & 1, C, a_off, b_off);
    }

    #pragma unroll
    for (int mt = 0; mt < 2; mt++)
        #pragma unroll
        for (int nt = 0; nt < 8; nt++) {
            int col = colBase + wn + nt * 8 + (lid & 3) * 2;
            float2 bv = *(const float2*)&bias[col];
            #pragma unroll
            for (int half = 0; half < 2; half++) {
                int row = rowBase + wm + mt * 16 + (lid >> 2) + half * 8;
                float2 v = make_float2(C[mt][nt][half * 2] + bv.x, C[mt][nt][half * 2 + 1] + bv.y);
                *(float2*)&out[(size_t)row * Cq + col] = v;
            }
        }
}

// ---------------- FA2 attention: fp16 single, 3-stage KV pipeline ----------
#define KVP 72
#define QBYTES (128*KVP*2)               // 18432
#define KVT (64*KVP*2)                   // 9216
#define KVSTAGE (2*KVT)                  // K, V
#define AOFF_KV QBYTES
#define ATTN_SMEM (QBYTES + 3*KVSTAGE)   // 73728

__global__ __launch_bounds__(256, 2) void attn_kernel() {
    extern __shared__ char smx[];
    uint32_t sb = smem_u32(smx);
    int tid = threadIdx.x, lid = tid & 31, wid = tid >> 5;
    int wm = wid * 16;
    int qt = blockIdx.x, head = blockIdx.y, b = blockIdx.z;
    size_t bh = (size_t)(b * Hq + head) * Nq * HDq;
    const fp16* Qg = g_q + bh + (size_t)qt * 128 * HDq;

    auto load_stage = [&](int kt, int slot) {
        uint32_t dst = sb + AOFF_KV + slot * KVSTAGE;
        const fp16* srcs[2] = {g_k + bh + (size_t)kt * 64 * HDq,
                               g_v + bh + (size_t)kt * 64 * HDq};
        #pragma unroll
        for (int t = 0; t < 2; t++)
            #pragma unroll
            for (int i = 0; i < 2; i++) {
                int idx = tid + 256 * i;
                int row = idx >> 3, seg = idx & 7;
                cp16(dst + t * KVT + (row * KVP + seg * 8) * 2,
                     srcs[t] + row * HDq + seg * 8);
            }
    };

    #pragma unroll
    for (int i = 0; i < 4; i++) {
        int idx = tid + 256 * i;
        int row = idx >> 3, seg = idx & 7;
        cp16(sb + (row * KVP + seg * 8) * 2, Qg + row * HDq + seg * 8);
    }
    load_stage(0, 0);
    cp_commit();
    load_stage(1, 1);
    cp_commit();

    float mA = -1e30f, mB = -1e30f, lA = 0.f, lB = 0.f;
    float co[8][4];
    #pragma unroll
    for (int j = 0; j < 8; j++)
        #pragma unroll
        for (int k = 0; k < 4; k++) co[j][k] = 0.f;

    uint32_t qfrag[4][4];

    for (int it = 0; it < 16; it++) {
        cp_wait<1>();
        __syncthreads();
        if (it == 0) {
            #pragma unroll
            for (int ks = 0; ks < 4; ks++) {
                int offq = ((wm + (lid & 15)) * KVP + ((lid >> 4) & 1) * 8 + ks * 16) * 2;
                ldsm4(qfrag[ks][0], qfrag[ks][1], qfrag[ks][2], qfrag[ks][3], sb + offq);
            }
        }
        if (it + 2 < 16) { load_stage(it + 2, (it + 2) % 3); cp_commit(); }
        else cp_commit();

        uint32_t kv = sb + AOFF_KV + (it % 3) * KVSTAGE;
        uint32_t aK = kv, aV = kv + KVT;

        float cs[8][4];
        #pragma unroll
        for (int j = 0; j < 8; j++)
            #pragma unroll
            for (int k = 0; k < 4; k++) cs[j][k] = 0.f;

        #pragma unroll
        for (int ks = 0; ks < 4; ks++) {
            int ko = ks * 16;
            uint32_t kh[8][2];
            #pragma unroll
            for (int p = 0; p < 4; p++) {
                int offb = ((p * 16 + ((lid >> 4) & 1) * 8 + (lid & 7)) * KVP
                            + ((lid >> 3) & 1) * 8 + ko) * 2;
                ldsm4(kh[2*p][0], kh[2*p][1], kh[2*p+1][0], kh[2*p+1][1], aK + offb);
            }
            #pragma unroll
            for (int nt = 0; nt < 8; nt++)
                mma_f16(cs[nt], qfrag[ks][0], qfrag[ks][1], qfrag[ks][2], qfrag[ks][3],
                        kh[nt][0], kh[nt][1]);
        }

        float mxA = -1e30f, mxB = -1e30f;
        #pragma unroll
        for (int nt = 0; nt < 8; nt++) {
            mxA = fmaxf(mxA, fmaxf(cs[nt][0], cs[nt][1]));
            mxB = fmaxf(mxB, fmaxf(cs[nt][2], cs[nt][3]));
        }
        mxA = fmaxf(mxA, __shfl_xor_sync(0xffffffffu, mxA, 1));
        mxA = fmaxf(mxA, __shfl_xor_sync(0xffffffffu, mxA, 2));
        mxB = fmaxf(mxB, __shfl_xor_sync(0xffffffffu, mxB, 1));
        mxB = fmaxf(mxB, __shfl_xor_sync(0xffffffffu, mxB, 2));
        float mnA = fmaxf(mA, mxA), mnB = fmaxf(mB, mxB);
        float alA = ex2(mA - mnA), alB = ex2(mB - mnB);
        float psA = 0.f, psB = 0.f;
        #pragma unroll
        for (int nt = 0; nt < 8; nt++) {
            cs[nt][0] = ex2(cs[nt][0] - mnA);
            cs[nt][1] = ex2(cs[nt][1] - mnA);
            cs[nt][2] = ex2(cs[nt][2] - mnB);
            cs[nt][3] = ex2(cs[nt][3] - mnB);
            psA += cs[nt][0] + cs[nt][1];
            psB += cs[nt][2] + cs[nt][3];
        }
        lA = lA * alA + psA; mA = mnA;
        lB = lB * alB + psB; mB = mnB;

        uint32_t pa[4][4];
        #pragma unroll
        for (int ks = 0; ks < 4; ks++) {
            #pragma unroll
            for (int half = 0; half < 2; half++) {
                int nt = 2 * ks + half;
                pa[ks][2 * half]     = pkh(cs[nt][0], cs[nt][1]);
                pa[ks][2 * half + 1] = pkh(cs[nt][2], cs[nt][3]);
            }
        }

        // alpha-skip: exact when no warp lane saw a new max (exp2(0)=1)
        if (!__all_sync(0xffffffffu, (alA == 1.f) && (alB == 1.f))) {
            #pragma unroll
            for (int nt = 0; nt < 8; nt++) {
                co[nt][0] *= alA; co[nt][1] *= alA;
                co[nt][2] *= alB; co[nt][3] *= alB;
            }
        }
        #pragma unroll
        for (int ks = 0; ks < 4; ks++) {
            int ko = ks * 16;
            uint32_t vh[8][2];
            #pragma unroll
            for (int dt = 0; dt < 4; dt++) {
                int offv = ((ko + (lid & 15)) * KVP + dt * 16 + ((lid >> 4) & 1) * 8) * 2;
                ldsm4t(vh[2*dt][0], vh[2*dt][1], vh[2*dt+1][0], vh[2*dt+1][1], aV + offv);
            }
            #pragma unroll
            for (int nt = 0; nt < 8; nt++)
                mma_f16(co[nt], pa[ks][0], pa[ks][1], pa[ks][2], pa[ks][3],
                        vh[nt][0], vh[nt][1]);
        }
    }

    lA += __shfl_xor_sync(0xffffffffu, lA, 1);
    lA += __shfl_xor_sync(0xffffffffu, lA, 2);
    lB += __shfl_xor_sync(0xffffffffu, lB, 1);
    lB += __shfl_xor_sync(0xffffffffu, lB, 2);

    float invA = 1.f / lA, invB = 1.f / lB;
    int rA = qt * 128 + wm + (lid >> 2);
    #pragma unroll
    for (int nt = 0; nt < 8; nt++) {
        int col = head * HDq + nt * 8 + (lid & 3) * 2;
        size_t base = (size_t)(b * Nq + rA) * Cq + col;
        *(uint32_t*)&g_att[base] = pkh(co[nt][0] * invA, co[nt][1] * invA);
        size_t base2 = (size_t)(b * Nq + rA + 8) * Cq + col;
        *(uint32_t*)&g_att[base2] = pkh(co[nt][2] * invB, co[nt][3] * invB);
    }
}

extern "C" void kernel_launch(void* const* d_in, const int* in_sizes, int n_in,
                              void* d_out, int out_size) {
    const float* x    = (const float*)d_in[0];
    const float* Wq   = (const float*)d_in[1];
    const float* Wk   = (const float*)d_in[2];
    const float* Wv   = (const float*)d_in[3];
    const float* Wp   = (const float*)d_in[4];
    const float* bp   = (const float*)d_in[5];
    const float* la_q = (const float*)d_in[6];
    const float* lb_q = (const float*)d_in[7];
    const float* la_k = (const float*)d_in[8];
    const float* lb_k = (const float*)d_in[9];
    const float* la_v = (const float*)d_in[10];
    const float* lb_v = (const float*)d_in[11];
    const float* bw   = (const float*)d_in[12];
    float* out = (float*)d_out;

    convert_x_kernel<<<(ROWS * Cq / 4 + 255) / 256, 256>>>(x);
    wprime_kernel<<<dim3(24, 24, 4), 256>>>(Wq, Wk, Wv, Wp,
                                            la_q, lb_q, la_k, lb_k, la_v, lb_v, bw);

    cudaFuncSetAttribute(gemm_qkv_kernel, cudaFuncAttributeMaxDynamicSharedMemorySize, GEMM_DSMEM);
    gemm_qkv_kernel<<<dim3(6, 64, 3), 256, GEMM_DSMEM>>>();

    cudaFuncSetAttribute(attn_kernel, cudaFuncAttributeMaxDynamicSharedMemorySize, ATTN_SMEM);
    attn_kernel<<<dim3(Nq / 128, Hq, Bq), 256, ATTN_SMEM>>>();

    cudaFuncSetAttribute(gemm_out_kernel, cudaFuncAttributeMaxDynamicSharedMemorySize, GEMM_DSMEM);
    gemm_out_kernel<<<dim3(6, 64), 256, GEMM_DSMEM>>>(bp, out);
}

// round 16
// speedup vs baseline: 2.5390x; 1.0272x over previous
#include <cuda_runtime.h>
#include <cuda_fp16.h>
#include <cstdint>

#define Bq 8
#define Nq 1024
#define Cq 768
#define Hq 12
#define HDq 64
#define Rq 16
#define ROWS (Bq*Nq)
#define QSCALE 0.18033688011112042f   // 0.125 * log2(e)

typedef __half fp16;

// ---------------- helpers ----------------
__device__ __forceinline__ uint32_t smem_u32(const void* p) {
    uint32_t a;
    asm("{ .reg .u64 t; cvta.to.shared.u64 t, %1; cvt.u32.u64 %0, t; }" : "=r"(a) : "l"(p));
    return a;
}
__device__ __forceinline__ void ldsm4(uint32_t& r0, uint32_t& r1, uint32_t& r2, uint32_t& r3,
                                      uint32_t addr) {
    asm volatile("ldmatrix.sync.aligned.m8n8.x4.shared.b16 {%0,%1,%2,%3}, [%4];"
                 : "=r"(r0), "=r"(r1), "=r"(r2), "=r"(r3) : "r"(addr));
}
__device__ __forceinline__ void ldsm4t(uint32_t& r0, uint32_t& r1, uint32_t& r2, uint32_t& r3,
                                       uint32_t addr) {
    asm volatile("ldmatrix.sync.aligned.m8n8.x4.trans.shared.b16 {%0,%1,%2,%3}, [%4];"
                 : "=r"(r0), "=r"(r1), "=r"(r2), "=r"(r3) : "r"(addr));
}
__device__ __forceinline__ void mma_f16(float* c, uint32_t a0, uint32_t a1, uint32_t a2,
                                        uint32_t a3, uint32_t b0, uint32_t b1) {
    asm("mma.sync.aligned.m16n8k16.row.col.f32.f16.f16.f32 "
        "{%0,%1,%2,%3}, {%4,%5,%6,%7}, {%8,%9}, {%0,%1,%2,%3};"
        : "+f"(c[0]), "+f"(c[1]), "+f"(c[2]), "+f"(c[3])
        : "r"(a0), "r"(a1), "r"(a2), "r"(a3), "r"(b0), "r"(b1));
}
__device__ __forceinline__ void cp16(uint32_t dst, const void* src) {
    asm volatile("cp.async.cg.shared.global [%0], [%1], 16;" :: "r"(dst), "l"(src));
}
__device__ __forceinline__ void cp_commit() {
    asm volatile("cp.async.commit_group;" ::: "memory");
}
template <int N>
__device__ __forceinline__ void cp_wait() {
    asm volatile("cp.async.wait_group %0;" :: "n"(N) : "memory");
}
__device__ __forceinline__ float ex2(float x) {
    float y; asm("ex2.approx.f32 %0, %1;" : "=f"(y) : "f"(x)); return y;
}
__device__ __forceinline__ uint32_t pkh(float a, float b) {
    __half2 t = __floats2half2_rn(a, b);
    return *(uint32_t*)&t;
}

// ---------------- scratch ----------------
__device__ fp16 g_q[Bq*Hq*Nq*HDq];                    // single, pre-scaled by QSCALE
__device__ fp16 g_k[Bq*Hq*Nq*HDq];
__device__ fp16 g_v[Bq*Hq*Nq*HDq];
__device__ fp16 g_X16[ROWS*Cq];
__device__ fp16 g_Wt[3][Cq*Cq];                       // (W + bw*la@lb)^T fp16
__device__ fp16 g_Wpt[Cq*Cq];
__device__ fp16 g_att[ROWS*Cq];

// ---------------- prep kernels ----------------
__global__ void convert_x_kernel(const float* __restrict__ X) {
    int i = blockIdx.x * blockDim.x + threadIdx.x;   // one float4 per thread
    if (i < ROWS * Cq / 4) {
        float4 v = ((const float4*)X)[i];
        uint32_t lo = pkh(v.x, v.y), hi = pkh(v.z, v.w);
        ((uint2*)g_X16)[i] = make_uint2(lo, hi);
    }
}

// W' = W + bw*(la@lb)  (sel<3), or plain Wp (sel=3); write transposed fp16
__global__ __launch_bounds__(256) void wprime_kernel(
        const float* __restrict__ Wq_, const float* __restrict__ Wk_,
        const float* __restrict__ Wv_, const float* __restrict__ Wp_,
        const float* __restrict__ laq, const float* __restrict__ lbq,
        const float* __restrict__ lak, const float* __restrict__ lbk,
        const float* __restrict__ lav, const float* __restrict__ lbv,
        const float* __restrict__ bw) {
    __shared__ float ws[32][33];
    __shared__ float las[32][16];
    __shared__ float lbs[16][33];
    int sel = blockIdx.z;
    const float* W  = (sel == 0) ? Wq_ : (sel == 1) ? Wk_ : (sel == 2) ? Wv_ : Wp_;
    const float* la = (sel == 0) ? laq : (sel == 1) ? lak : lav;
    const float* lb = (sel == 0) ? lbq : (sel == 1) ? lbk : lbv;
    fp16* dh = (sel < 3) ? g_Wt[sel] : g_Wpt;
    int tid = threadIdx.x, tx = tid & 31, ty = tid >> 5;
    int kb = blockIdx.y * 32, nb = blockIdx.x * 32;
    #pragma unroll
    for (int s = 0; s < 4; s++)
        ws[ty + 8 * s][tx] = W[(size_t)(kb + ty + 8 * s) * Cq + nb + tx];
    if (sel < 3) {
        for (int l = tid; l < 512; l += 256) {
            las[l >> 4][l & 15] = la[(size_t)(kb + (l >> 4)) * Rq + (l & 15)];
            lbs[l >> 5][l & 31] = lb[(size_t)(l >> 5) * Cq + nb + (l & 31)];
        }
        __syncthreads();
        float w = bw[sel];
        #pragma unroll
        for (int s = 0; s < 4; s++) {
            int i = ty + 8 * s;
            float acc = 0.f;
            #pragma unroll
            for (int r = 0; r < Rq; r++) acc = fmaf(las[i][r], lbs[r][tx], acc);
            ws[i][tx] = fmaf(w, acc, ws[i][tx]);
        }
    }
    __syncthreads();
    #pragma unroll
    for (int s = 0; s < 4; s++) {
        float v = ws[tx][ty + 8 * s];
        dh[(size_t)(nb + ty + 8 * s) * Cq + kb + tx] = __float2half_rn(v);
    }
}

// ---------------- pipelined fp16 GEMM core: K-chunk 64, 2 stages, 2 CTAs/SM ----------------
#define GP 72
#define GTILE_B (128*GP*2)                 // 18432
#define GSTAGE_B (2*GTILE_B)               // A, B = 36864
#define GEMM_DSMEM (2*GSTAGE_B)            // 73728

__device__ __forceinline__ void issue_chunk(uint32_t sbase, int stage,
                                            const fp16* a, const fp16* b,
                                            int stride, int tid) {
    uint32_t st = sbase + stage * GSTAGE_B;
    const fp16* srcs[2] = {a, b};
    #pragma unroll
    for (int t = 0; t < 2; t++) {
        #pragma unroll
        for (int i = 0; i < 4; i++) {
            int idx = tid + 256 * i;
            int row = idx >> 3, seg = idx & 7;
            cp16(st + t * GTILE_B + (row * GP + seg * 8) * 2,
                 srcs[t] + (size_t)row * stride + seg * 8);
        }
    }
    cp_commit();
}

__device__ __forceinline__ void compute_chunk(uint32_t sbase, int stage,
                                              float C[2][8][4], int a_off, int b_off) {
    uint32_t st = sbase + stage * GSTAGE_B;
    uint32_t aB = st, bB = st + GTILE_B;
    #pragma unroll
    for (int kt = 0; kt < 4; kt++) {
        int ko = kt * 16;
        uint32_t ah[2][4], bh[8][2];
        #pragma unroll
        for (int mt = 0; mt < 2; mt++) {
            int off = (a_off + mt * 16 * GP + ko) * 2;
            ldsm4(ah[mt][0], ah[mt][1], ah[mt][2], ah[mt][3], aB + off);
        }
        #pragma unroll
        for (int p = 0; p < 4; p++) {
            int off = (b_off + p * 16 * GP + ko) * 2;
            ldsm4(bh[2*p][0], bh[2*p][1], bh[2*p+1][0], bh[2*p+1][1], bB + off);
        }
        #pragma unroll
        for (int mt = 0; mt < 2; mt++)
            #pragma unroll
            for (int nt = 0; nt < 8; nt++)
                mma_f16(C[mt][nt], ah[mt][0], ah[mt][1], ah[mt][2], ah[mt][3],
                        bh[nt][0], bh[nt][1]);
    }
}

// ---------------- qkv GEMM: 1-pass -> q,k,v single fp16 head-split ----------------
__global__ __launch_bounds__(256, 2) void gemm_qkv_kernel() {
    extern __shared__ char dsm[];
    uint32_t sbase = smem_u32(dsm);
    int tid = threadIdx.x, lid = tid & 31, wid = tid >> 5;
    int wm = (wid & 3) * 32, wn = (wid >> 2) * 64;
    int type = blockIdx.z;
    int rowBase = blockIdx.y * 128, colBase = blockIdx.x * 128;

    const fp16* Xp = g_X16 + (size_t)rowBase * Cq;
    const fp16* Wp = g_Wt[type] + (size_t)colBase * Cq;

    float C[2][8][4];
    #pragma unroll
    for (int i = 0; i < 2; i++)
        #pragma unroll
        for (int j = 0; j < 8; j++)
            #pragma unroll
            for (int k = 0; k < 4; k++) C[i][j][k] = 0.f;

    int a_off = (wm + (lid & 15)) * GP + ((lid >> 4) & 1) * 8;
    int b_off = (wn + ((lid >> 4) & 1) * 8 + (lid & 7)) * GP + ((lid >> 3) & 1) * 8;

    const int NCH = 12;
    issue_chunk(sbase, 0, Xp, Wp, Cq, tid);
    for (int c = 0; c < NCH; c++) {
        cp_wait<0>();
        __syncthreads();
        int nc = c + 1;
        if (nc < NCH)
            issue_chunk(sbase, nc & 1, Xp + nc * 64, Wp + nc * 64, Cq, tid);
        compute_chunk(sbase, c & 1, C, a_off, b_off);
    }

    fp16* dst = (type == 0) ? g_q : (type == 1) ? g_k : g_v;
    float scl = (type == 0) ? QSCALE : 1.f;
    #pragma unroll
    for (int mt = 0; mt < 2; mt++)
        #pragma unroll
        for (int nt = 0; nt < 8; nt++) {
            int col = colBase + wn + nt * 8 + (lid & 3) * 2;
            int h = col >> 6, hd = col & 63;
            #pragma unroll
            for (int half = 0; half < 2; half++) {
                int row = rowBase + wm + mt * 16 + (lid >> 2) + half * 8;
                int b_ = row >> 10, n = row & 1023;
                float v0 = C[mt][nt][half * 2] * scl, v1 = C[mt][nt][half * 2 + 1] * scl;
                size_t base = (((size_t)(b_ * Hq + h) * Nq) + n) * HDq + hd;
                *(uint32_t*)&dst[base] = pkh(v0, v1);
            }
        }
}

// ---------------- output projection GEMM + bias (1-pass) ----------------
__global__ __launch_bounds__(256, 2) void gemm_out_kernel(const float* __restrict__ bias,
                                                          float* __restrict__ out) {
    extern __shared__ char dsm[];
    uint32_t sbase = smem_u32(dsm);
    int tid = threadIdx.x, lid = tid & 31, wid = tid >> 5;
    int wm = (wid & 3) * 32, wn = (wid >> 2) * 64;
    int rowBase = blockIdx.y * 128, colBase = blockIdx.x * 128;

    const fp16* Ap = g_att + (size_t)rowBase * Cq;
    const fp16* Wp = g_Wpt + (size_t)colBase * Cq;

    float C[2][8][4];
    #pragma unroll
    for (int i = 0; i < 2; i++)
        #pragma unroll
        for (int j = 0; j < 8; j++)
            #pragma unroll
            for (int k = 0; k < 4; k++) C[i][j][k] = 0.f;

    int a_off = (wm + (lid & 15)) * GP + ((lid >> 4) & 1) * 8;
    int b_off = (wn + ((lid >> 4) & 1) * 8 + (lid & 7)) * GP + ((lid >> 3) & 1) * 8;

    const int NCH = 12;
    issue_chunk(sbase, 0, Ap, Wp, Cq, tid);
    for (int c = 0; c < NCH; c++) {
        cp_wait<0>();
        __syncthreads();
        int nc = c + 1;
        if (nc < NCH)
            issue_chunk(sbase, nc & 1, Ap + nc * 64, Wp + nc * 64, Cq, tid);
        compute_chunk(sbase, c & 1, C, a_off, b_off);
    }

    #pragma unroll
    for (int mt = 0; mt < 2; mt++)
        #pragma unroll
        for (int nt = 0; nt < 8; nt++) {
            int col = colBase + wn + nt * 8 + (lid & 3) * 2;
            float2 bv = *(const float2*)&bias[col];
            #pragma unroll
            for (int half = 0; half < 2; half++) {
                int row = rowBase + wm + mt * 16 + (lid >> 2) + half * 8;
                float2 v = make_float2(C[mt][nt][half * 2] + bv.x, C[mt][nt][half * 2 + 1] + bv.y);
                *(float2*)&out[(size_t)row * Cq + col] = v;
            }
        }
}

// ---------------- FA2 attention: fp16 single, 3-stage KV pipeline ----------
#define KVP 72
#define QBYTES (128*KVP*2)               // 18432
#define KVT (64*KVP*2)                   // 9216
#define KVSTAGE (2*KVT)                  // K, V
#define AOFF_KV QBYTES
#define ATTN_SMEM (QBYTES + 3*KVSTAGE)   // 73728

__global__ __launch_bounds__(256, 2) void attn_kernel() {
    extern __shared__ char smx[];
    uint32_t sb = smem_u32(smx);
    int tid = threadIdx.x, lid = tid & 31, wid = tid >> 5;
    int wm = wid * 16;
    int qt = blockIdx.x, head = blockIdx.y, b = blockIdx.z;
    size_t bh = (size_t)(b * Hq + head) * Nq * HDq;
    const fp16* Qg = g_q + bh + (size_t)qt * 128 * HDq;

    auto load_stage = [&](int kt, int slot) {
        uint32_t dst = sb + AOFF_KV + slot * KVSTAGE;
        const fp16* srcs[2] = {g_k + bh + (size_t)kt * 64 * HDq,
                               g_v + bh + (size_t)kt * 64 * HDq};
        #pragma unroll
        for (int t = 0; t < 2; t++)
            #pragma unroll
            for (int i = 0; i < 2; i++) {
                int idx = tid + 256 * i;
                int row = idx >> 3, seg = idx & 7;
                cp16(dst + t * KVT + (row * KVP + seg * 8) * 2,
                     srcs[t] + row * HDq + seg * 8);
            }
    };

    #pragma unroll
    for (int i = 0; i < 4; i++) {
        int idx = tid + 256 * i;
        int row = idx >> 3, seg = idx & 7;
        cp16(sb + (row * KVP + seg * 8) * 2, Qg + row * HDq + seg * 8);
    }
    load_stage(0, 0);
    cp_commit();
    load_stage(1, 1);
    cp_commit();

    float mA = -1e30f, mB = -1e30f, lA = 0.f, lB = 0.f;
    float co[8][4];
    #pragma unroll
    for (int j = 0; j < 8; j++)
        #pragma unroll
        for (int k = 0; k < 4; k++) co[j][k] = 0.f;

    uint32_t qfrag[4][4];

    for (int it = 0; it < 16; it++) {
        cp_wait<1>();
        __syncthreads();
        if (it == 0) {
            #pragma unroll
            for (int ks = 0; ks < 4; ks++) {
                int offq = ((wm + (lid & 15)) * KVP + ((lid >> 4) & 1) * 8 + ks * 16) * 2;
                ldsm4(qfrag[ks][0], qfrag[ks][1], qfrag[ks][2], qfrag[ks][3], sb + offq);
            }
        }
        if (it + 2 < 16) { load_stage(it + 2, (it + 2) % 3); cp_commit(); }
        else cp_commit();

        uint32_t kv = sb + AOFF_KV + (it % 3) * KVSTAGE;
        uint32_t aK = kv, aV = kv + KVT;

        float cs[8][4];
        #pragma unroll
        for (int j = 0; j < 8; j++)
            #pragma unroll
            for (int k = 0; k < 4; k++) cs[j][k] = 0.f;

        #pragma unroll
        for (int ks = 0; ks < 4; ks++) {
            int ko = ks * 16;
            uint32_t kh[8][2];
            #pragma unroll
            for (int p = 0; p < 4; p++) {
                int offb = ((p * 16 + ((lid >> 4) & 1) * 8 + (lid & 7)) * KVP
                            + ((lid >> 3) & 1) * 8 + ko) * 2;
                ldsm4(kh[2*p][0], kh[2*p][1], kh[2*p+1][0], kh[2*p+1][1], aK + offb);
            }
            #pragma unroll
            for (int nt = 0; nt < 8; nt++)
                mma_f16(cs[nt], qfrag[ks][0], qfrag[ks][1], qfrag[ks][2], qfrag[ks][3],
                        kh[nt][0], kh[nt][1]);
        }

        float mxA = -1e30f, mxB = -1e30f;
        #pragma unroll
        for (int nt = 0; nt < 8; nt++) {
            mxA = fmaxf(mxA, fmaxf(cs[nt][0], cs[nt][1]));
            mxB = fmaxf(mxB, fmaxf(cs[nt][2], cs[nt][3]));
        }
        mxA = fmaxf(mxA, __shfl_xor_sync(0xffffffffu, mxA, 1));
        mxA = fmaxf(mxA, __shfl_xor_sync(0xffffffffu, mxA, 2));
        mxB = fmaxf(mxB, __shfl_xor_sync(0xffffffffu, mxB, 1));
        mxB = fmaxf(mxB, __shfl_xor_sync(0xffffffffu, mxB, 2));
        float mnA = fmaxf(mA, mxA), mnB = fmaxf(mB, mxB);
        float alA = ex2(mA - mnA), alB = ex2(mB - mnB);
        float psA = 0.f, psB = 0.f;
        #pragma unroll
        for (int nt = 0; nt < 8; nt++) {
            cs[nt][0] = ex2(cs[nt][0] - mnA);
            cs[nt][1] = ex2(cs[nt][1] - mnA);
            cs[nt][2] = ex2(cs[nt][2] - mnB);
            cs[nt][3] = ex2(cs[nt][3] - mnB);
            psA += cs[nt][0] + cs[nt][1];
            psB += cs[nt][2] + cs[nt][3];
        }
        lA = lA * alA + psA; mA = mnA;
        lB = lB * alB + psB; mB = mnB;

        uint32_t pa[4][4];
        #pragma unroll
        for (int ks = 0; ks < 4; ks++) {
            #pragma unroll
            for (int half = 0; half < 2; half++) {
                int nt = 2 * ks + half;
                pa[ks][2 * half]     = pkh(cs[nt][0], cs[nt][1]);
                pa[ks][2 * half + 1] = pkh(cs[nt][2], cs[nt][3]);
            }
        }

        #pragma unroll
        for (int nt = 0; nt < 8; nt++) {
            co[nt][0] *= alA; co[nt][1] *= alA;
            co[nt][2] *= alB; co[nt][3] *= alB;
        }
        #pragma unroll
        for (int ks = 0; ks < 4; ks++) {
            int ko = ks * 16;
            uint32_t vh[8][2];
            #pragma unroll
            for (int dt = 0; dt < 4; dt++) {
                int offv = ((ko + (lid & 15)) * KVP + dt * 16 + ((lid >> 4) & 1) * 8) * 2;
                ldsm4t(vh[2*dt][0], vh[2*dt][1], vh[2*dt+1][0], vh[2*dt+1][1], aV + offv);
            }
            #pragma unroll
            for (int nt = 0; nt < 8; nt++)
                mma_f16(co[nt], pa[ks][0], pa[ks][1], pa[ks][2], pa[ks][3],
                        vh[nt][0], vh[nt][1]);
        }
    }

    lA += __shfl_xor_sync(0xffffffffu, lA, 1);
    lA += __shfl_xor_sync(0xffffffffu, lA, 2);
    lB += __shfl_xor_sync(0xffffffffu, lB, 1);
    lB += __shfl_xor_sync(0xffffffffu, lB, 2);

    float invA = 1.f / lA, invB = 1.f / lB;
    int rA = qt * 128 + wm + (lid >> 2);
    #pragma unroll
    for (int nt = 0; nt < 8; nt++) {
        int col = head * HDq + nt * 8 + (lid & 3) * 2;
        size_t base = (size_t)(b * Nq + rA) * Cq + col;
        *(uint32_t*)&g_att[base] = pkh(co[nt][0] * invA, co[nt][1] * invA);
        size_t base2 = (size_t)(b * Nq + rA + 8) * Cq + col;
        *(uint32_t*)&g_att[base2] = pkh(co[nt][2] * invB, co[nt][3] * invB);
    }
}

extern "C" void kernel_launch(void* const* d_in, const int* in_sizes, int n_in,
                              void* d_out, int out_size) {
    const float* x    = (const float*)d_in[0];
    const float* Wq   = (const float*)d_in[1];
    const float* Wk   = (const float*)d_in[2];
    const float* Wv   = (const float*)d_in[3];
    const float* Wp   = (const float*)d_in[4];
    const float* bp   = (const float*)d_in[5];
    const float* la_q = (const float*)d_in[6];
    const float* lb_q = (const float*)d_in[7];
    const float* la_k = (const float*)d_in[8];
    const float* lb_k = (const float*)d_in[9];
    const float* la_v = (const float*)d_in[10];
    const float* lb_v = (const float*)d_in[11];
    const float* bw   = (const float*)d_in[12];
    float* out = (float*)d_out;

    convert_x_kernel<<<(ROWS * Cq / 4 + 255) / 256, 256>>>(x);
    wprime_kernel<<<dim3(24, 24, 4), 256>>>(Wq, Wk, Wv, Wp,
                                            la_q, lb_q, la_k, lb_k, la_v, lb_v, bw);

    cudaFuncSetAttribute(gemm_qkv_kernel, cudaFuncAttributeMaxDynamicSharedMemorySize, GEMM_DSMEM);
    gemm_qkv_kernel<<<dim3(6, 64, 3), 256, GEMM_DSMEM>>>();

    cudaFuncSetAttribute(attn_kernel, cudaFuncAttributeMaxDynamicSharedMemorySize, ATTN_SMEM);
    attn_kernel<<<dim3(Nq / 128, Hq, Bq), 256, ATTN_SMEM>>>();

    cudaFuncSetAttribute(gemm_out_kernel, cudaFuncAttributeMaxDynamicSharedMemorySize, GEMM_DSMEM);
    gemm_out_kernel<<<dim3(6, 64), 256, GEMM_DSMEM>>>(bp, out);
}

// round 17
// speedup vs baseline: 2.5990x; 1.0236x over previous
#include <cuda_runtime.h>
#include <cuda_fp16.h>
#include <cstdint>

#define Bq 8
#define Nq 1024
#define Cq 768
#define Hq 12
#define HDq 64
#define Rq 16
#define ROWS (Bq*Nq)
#define QSCALE 0.18033688011112042f   // 0.125 * log2(e)

typedef __half fp16;

// ---------------- helpers ----------------
__device__ __forceinline__ uint32_t smem_u32(const void* p) {
    uint32_t a;
    asm("{ .reg .u64 t; cvta.to.shared.u64 t, %1; cvt.u32.u64 %0, t; }" : "=r"(a) : "l"(p));
    return a;
}
__device__ __forceinline__ void ldsm4(uint32_t& r0, uint32_t& r1, uint32_t& r2, uint32_t& r3,
                                      uint32_t addr) {
    asm volatile("ldmatrix.sync.aligned.m8n8.x4.shared.b16 {%0,%1,%2,%3}, [%4];"
                 : "=r"(r0), "=r"(r1), "=r"(r2), "=r"(r3) : "r"(addr));
}
__device__ __forceinline__ void ldsm4t(uint32_t& r0, uint32_t& r1, uint32_t& r2, uint32_t& r3,
                                       uint32_t addr) {
    asm volatile("ldmatrix.sync.aligned.m8n8.x4.trans.shared.b16 {%0,%1,%2,%3}, [%4];"
                 : "=r"(r0), "=r"(r1), "=r"(r2), "=r"(r3) : "r"(addr));
}
__device__ __forceinline__ void mma_f16(float* c, uint32_t a0, uint32_t a1, uint32_t a2,
                                        uint32_t a3, uint32_t b0, uint32_t b1) {
    asm("mma.sync.aligned.m16n8k16.row.col.f32.f16.f16.f32 "
        "{%0,%1,%2,%3}, {%4,%5,%6,%7}, {%8,%9}, {%0,%1,%2,%3};"
        : "+f"(c[0]), "+f"(c[1]), "+f"(c[2]), "+f"(c[3])
        : "r"(a0), "r"(a1), "r"(a2), "r"(a3), "r"(b0), "r"(b1));
}
__device__ __forceinline__ void cp16(uint32_t dst, const void* src) {
    asm volatile("cp.async.cg.shared.global [%0], [%1], 16;" :: "r"(dst), "l"(src));
}
__device__ __forceinline__ void cp_commit() {
    asm volatile("cp.async.commit_group;" ::: "memory");
}
template <int N>
__device__ __forceinline__ void cp_wait() {
    asm volatile("cp.async.wait_group %0;" :: "n"(N) : "memory");
}
__device__ __forceinline__ float ex2(float x) {
    float y; asm("ex2.approx.f32 %0, %1;" : "=f"(y) : "f"(x)); return y;
}
__device__ __forceinline__ uint32_t ex2h2(uint32_t x) {
    uint32_t y; asm("ex2.approx.f16x2 %0, %1;" : "=r"(y) : "r"(x)); return y;
}
__device__ __forceinline__ uint32_t pkh(float a, float b) {
    __half2 t = __floats2half2_rn(a, b);
    return *(uint32_t*)&t;
}

// ---------------- scratch ----------------
__device__ fp16 g_q[Bq*Hq*Nq*HDq];                    // single, pre-scaled by QSCALE
__device__ fp16 g_k[Bq*Hq*Nq*HDq];
__device__ fp16 g_v[Bq*Hq*Nq*HDq];
__device__ fp16 g_X16[ROWS*Cq];
__device__ fp16 g_Wt[3][Cq*Cq];                       // (W + bw*la@lb)^T fp16
__device__ fp16 g_Wpt[Cq*Cq];
__device__ fp16 g_att[ROWS*Cq];

// ---------------- prep kernels ----------------
__global__ void convert_x_kernel(const float* __restrict__ X) {
    int i = blockIdx.x * blockDim.x + threadIdx.x;   // one float4 per thread
    if (i < ROWS * Cq / 4) {
        float4 v = ((const float4*)X)[i];
        uint32_t lo = pkh(v.x, v.y), hi = pkh(v.z, v.w);
        ((uint2*)g_X16)[i] = make_uint2(lo, hi);
    }
}

// W' = W + bw*(la@lb)  (sel<3), or plain Wp (sel=3); write transposed fp16
__global__ __launch_bounds__(256) void wprime_kernel(
        const float* __restrict__ Wq_, const float* __restrict__ Wk_,
        const float* __restrict__ Wv_, const float* __restrict__ Wp_,
        const float* __restrict__ laq, const float* __restrict__ lbq,
        const float* __restrict__ lak, const float* __restrict__ lbk,
        const float* __restrict__ lav, const float* __restrict__ lbv,
        const float* __restrict__ bw) {
    __shared__ float ws[32][33];
    __shared__ float las[32][16];
    __shared__ float lbs[16][33];
    int sel = blockIdx.z;
    const float* W  = (sel == 0) ? Wq_ : (sel == 1) ? Wk_ : (sel == 2) ? Wv_ : Wp_;
    const float* la = (sel == 0) ? laq : (sel == 1) ? lak : lav;
    const float* lb = (sel == 0) ? lbq : (sel == 1) ? lbk : lbv;
    fp16* dh = (sel < 3) ? g_Wt[sel] : g_Wpt;
    int tid = threadIdx.x, tx = tid & 31, ty = tid >> 5;
    int kb = blockIdx.y * 32, nb = blockIdx.x * 32;
    #pragma unroll
    for (int s = 0; s < 4; s++)
        ws[ty + 8 * s][tx] = W[(size_t)(kb + ty + 8 * s) * Cq + nb + tx];
    if (sel < 3) {
        for (int l = tid; l < 512; l += 256) {
            las[l >> 4][l & 15] = la[(size_t)(kb + (l >> 4)) * Rq + (l & 15)];
            lbs[l >> 5][l & 31] = lb[(size_t)(l >> 5) * Cq + nb + (l & 31)];
        }
        __syncthreads();
        float w = bw[sel];
        #pragma unroll
        for (int s = 0; s < 4; s++) {
            int i = ty + 8 * s;
            float acc = 0.f;
            #pragma unroll
            for (int r = 0; r < Rq; r++) acc = fmaf(las[i][r], lbs[r][tx], acc);
            ws[i][tx] = fmaf(w, acc, ws[i][tx]);
        }
    }
    __syncthreads();
    #pragma unroll
    for (int s = 0; s < 4; s++) {
        float v = ws[tx][ty + 8 * s];
        dh[(size_t)(nb + ty + 8 * s) * Cq + kb + tx] = __float2half_rn(v);
    }
}

// ---------------- pipelined fp16 GEMM core: K-chunk 64, 2 stages, 2 CTAs/SM ----------------
#define GP 72
#define GTILE_B (128*GP*2)                 // 18432
#define GSTAGE_B (2*GTILE_B)               // A, B = 36864
#define GEMM_DSMEM (2*GSTAGE_B)            // 73728

__device__ __forceinline__ void issue_chunk(uint32_t sbase, int stage,
                                            const fp16* a, const fp16* b,
                                            int stride, int tid) {
    uint32_t st = sbase + stage * GSTAGE_B;
    const fp16* srcs[2] = {a, b};
    #pragma unroll
    for (int t = 0; t < 2; t++) {
        #pragma unroll
        for (int i = 0; i < 4; i++) {
            int idx = tid + 256 * i;
            int row = idx >> 3, seg = idx & 7;
            cp16(st + t * GTILE_B + (row * GP + seg * 8) * 2,
                 srcs[t] + (size_t)row * stride + seg * 8);
        }
    }
    cp_commit();
}

__device__ __forceinline__ void compute_chunk(uint32_t sbase, int stage,
                                              float C[2][8][4], int a_off, int b_off) {
    uint32_t st = sbase + stage * GSTAGE_B;
    uint32_t aB = st, bB = st + GTILE_B;
    #pragma unroll
    for (int kt = 0; kt < 4; kt++) {
        int ko = kt * 16;
        uint32_t ah[2][4], bh[8][2];
        #pragma unroll
        for (int mt = 0; mt < 2; mt++) {
            int off = (a_off + mt * 16 * GP + ko) * 2;
            ldsm4(ah[mt][0], ah[mt][1], ah[mt][2], ah[mt][3], aB + off);
        }
        #pragma unroll
        for (int p = 0; p < 4; p++) {
            int off = (b_off + p * 16 * GP + ko) * 2;
            ldsm4(bh[2*p][0], bh[2*p][1], bh[2*p+1][0], bh[2*p+1][1], bB + off);
        }
        #pragma unroll
        for (int mt = 0; mt < 2; mt++)
            #pragma unroll
            for (int nt = 0; nt < 8; nt++)
                mma_f16(C[mt][nt], ah[mt][0], ah[mt][1], ah[mt][2], ah[mt][3],
                        bh[nt][0], bh[nt][1]);
    }
}

// ---------------- qkv GEMM: 1-pass -> q,k,v single fp16 head-split ----------------
__global__ __launch_bounds__(256, 2) void gemm_qkv_kernel() {
    extern __shared__ char dsm[];
    uint32_t sbase = smem_u32(dsm);
    int tid = threadIdx.x, lid = tid & 31, wid = tid >> 5;
    int wm = (wid & 3) * 32, wn = (wid >> 2) * 64;
    int type = blockIdx.z;
    int rowBase = blockIdx.y * 128, colBase = blockIdx.x * 128;

    const fp16* Xp = g_X16 + (size_t)rowBase * Cq;
    const fp16* Wp = g_Wt[type] + (size_t)colBase * Cq;

    float C[2][8][4];
    #pragma unroll
    for (int i = 0; i < 2; i++)
        #pragma unroll
        for (int j = 0; j < 8; j++)
            #pragma unroll
            for (int k = 0; k < 4; k++) C[i][j][k] = 0.f;

    int a_off = (wm + (lid & 15)) * GP + ((lid >> 4) & 1) * 8;
    int b_off = (wn + ((lid >> 4) & 1) * 8 + (lid & 7)) * GP + ((lid >> 3) & 1) * 8;

    const int NCH = 12;
    issue_chunk(sbase, 0, Xp, Wp, Cq, tid);
    for (int c = 0; c < NCH; c++) {
        cp_wait<0>();
        __syncthreads();
        int nc = c + 1;
        if (nc < NCH)
            issue_chunk(sbase, nc & 1, Xp + nc * 64, Wp + nc * 64, Cq, tid);
        compute_chunk(sbase, c & 1, C, a_off, b_off);
    }

    fp16* dst = (type == 0) ? g_q : (type == 1) ? g_k : g_v;
    float scl = (type == 0) ? QSCALE : 1.f;
    #pragma unroll
    for (int mt = 0; mt < 2; mt++)
        #pragma unroll
        for (int nt = 0; nt < 8; nt++) {
            int col = colBase + wn + nt * 8 + (lid & 3) * 2;
            int h = col >> 6, hd = col & 63;
            #pragma unroll
            for (int half = 0; half < 2; half++) {
                int row = rowBase + wm + mt * 16 + (lid >> 2) + half * 8;
                int b_ = row >> 10, n = row & 1023;
                float v0 = C[mt][nt][half * 2] * scl, v1 = C[mt][nt][half * 2 + 1] * scl;
                size_t base = (((size_t)(b_ * Hq + h) * Nq) + n) * HDq + hd;
                *(uint32_t*)&dst[base] = pkh(v0, v1);
            }
        }
}

// ---------------- output projection GEMM + bias (1-pass) ----------------
__global__ __launch_bounds__(256, 2) void gemm_out_kernel(const float* __restrict__ bias,
                                                          float* __restrict__ out) {
    extern __shared__ char dsm[];
    uint32_t sbase = smem_u32(dsm);
    int tid = threadIdx.x, lid = tid & 31, wid = tid >> 5;
    int wm = (wid & 3) * 32, wn = (wid >> 2) * 64;
    int rowBase = blockIdx.y * 128, colBase = blockIdx.x * 128;

    const fp16* Ap = g_att + (size_t)rowBase * Cq;
    const fp16* Wp = g_Wpt + (size_t)colBase * Cq;

    float C[2][8][4];
    #pragma unroll
    for (int i = 0; i < 2; i++)
        #pragma unroll
        for (int j = 0; j < 8; j++)
            #pragma unroll
            for (int k = 0; k < 4; k++) C[i][j][k] = 0.f;

    int a_off = (wm + (lid & 15)) * GP + ((lid >> 4) & 1) * 8;
    int b_off = (wn + ((lid >> 4) & 1) * 8 + (lid & 7)) * GP + ((lid >> 3) & 1) * 8;

    const int NCH = 12;
    issue_chunk(sbase, 0, Ap, Wp, Cq, tid);
    for (int c = 0; c < NCH; c++) {
        cp_wait<0>();
        __syncthreads();
        int nc = c + 1;
        if (nc < NCH)
            issue_chunk(sbase, nc & 1, Ap + nc * 64, Wp + nc * 64, Cq, tid);
        compute_chunk(sbase, c & 1, C, a_off, b_off);
    }

    #pragma unroll
    for (int mt = 0; mt < 2; mt++)
        #pragma unroll
        for (int nt = 0; nt < 8; nt++) {
            int col = colBase + wn + nt * 8 + (lid & 3) * 2;
            float2 bv = *(const float2*)&bias[col];
            #pragma unroll
            for (int half = 0; half < 2; half++) {
                int row = rowBase + wm + mt * 16 + (lid >> 2) + half * 8;
                float2 v = make_float2(C[mt][nt][half * 2] + bv.x, C[mt][nt][half * 2 + 1] + bv.y);
                *(float2*)&out[(size_t)row * Cq + col] = v;
            }
        }
}

// ---------------- FA2 attention: fp16 single, f16x2 exp, 3-stage KV pipeline ----------
#define KVP 72
#define QBYTES (128*KVP*2)               // 18432
#define KVT (64*KVP*2)                   // 9216
#define KVSTAGE (2*KVT)                  // K, V
#define AOFF_KV QBYTES
#define ATTN_SMEM (QBYTES + 3*KVSTAGE)   // 73728

__global__ __launch_bounds__(256, 2) void attn_kernel() {
    extern __shared__ char smx[];
    uint32_t sb = smem_u32(smx);
    int tid = threadIdx.x, lid = tid & 31, wid = tid >> 5;
    int wm = wid * 16;
    int qt = blockIdx.x, head = blockIdx.y, b = blockIdx.z;
    size_t bh = (size_t)(b * Hq + head) * Nq * HDq;
    const fp16* Qg = g_q + bh + (size_t)qt * 128 * HDq;

    auto load_stage = [&](int kt, int slot) {
        uint32_t dst = sb + AOFF_KV + slot * KVSTAGE;
        const fp16* srcs[2] = {g_k + bh + (size_t)kt * 64 * HDq,
                               g_v + bh + (size_t)kt * 64 * HDq};
        #pragma unroll
        for (int t = 0; t < 2; t++)
            #pragma unroll
            for (int i = 0; i < 2; i++) {
                int idx = tid + 256 * i;
                int row = idx >> 3, seg = idx & 7;
                cp16(dst + t * KVT + (row * KVP + seg * 8) * 2,
                     srcs[t] + row * HDq + seg * 8);
            }
    };

    #pragma unroll
    for (int i = 0; i < 4; i++) {
        int idx = tid + 256 * i;
        int row = idx >> 3, seg = idx & 7;
        cp16(sb + (row * KVP + seg * 8) * 2, Qg + row * HDq + seg * 8);
    }
    load_stage(0, 0);
    cp_commit();
    load_stage(1, 1);
    cp_commit();

    float mA = -1e30f, mB = -1e30f, lA = 0.f, lB = 0.f;
    float co[8][4];
    #pragma unroll
    for (int j = 0; j < 8; j++)
        #pragma unroll
        for (int k = 0; k < 4; k++) co[j][k] = 0.f;

    uint32_t qfrag[4][4];

    for (int it = 0; it < 16; it++) {
        cp_wait<1>();
        __syncthreads();
        if (it == 0) {
            #pragma unroll
            for (int ks = 0; ks < 4; ks++) {
                int offq = ((wm + (lid & 15)) * KVP + ((lid >> 4) & 1) * 8 + ks * 16) * 2;
                ldsm4(qfrag[ks][0], qfrag[ks][1], qfrag[ks][2], qfrag[ks][3], sb + offq);
            }
        }
        if (it + 2 < 16) { load_stage(it + 2, (it + 2) % 3); cp_commit(); }
        else cp_commit();

        uint32_t kv = sb + AOFF_KV + (it % 3) * KVSTAGE;
        uint32_t aK = kv, aV = kv + KVT;

        float cs[8][4];
        #pragma unroll
        for (int j = 0; j < 8; j++)
            #pragma unroll
            for (int k = 0; k < 4; k++) cs[j][k] = 0.f;

        #pragma unroll
        for (int ks = 0; ks < 4; ks++) {
            int ko = ks * 16;
            uint32_t kh[8][2];
            #pragma unroll
            for (int p = 0; p < 4; p++) {
                int offb = ((p * 16 + ((lid >> 4) & 1) * 8 + (lid & 7)) * KVP
                            + ((lid >> 3) & 1) * 8 + ko) * 2;
                ldsm4(kh[2*p][0], kh[2*p][1], kh[2*p+1][0], kh[2*p+1][1], aK + offb);
            }
            #pragma unroll
            for (int nt = 0; nt < 8; nt++)
                mma_f16(cs[nt], qfrag[ks][0], qfrag[ks][1], qfrag[ks][2], qfrag[ks][3],
                        kh[nt][0], kh[nt][1]);
        }

        // ---- softmax: fp32 max reduce, then exp + repack fused via ex2.f16x2 ----
        float mxA = -1e30f, mxB = -1e30f;
        #pragma unroll
        for (int nt = 0; nt < 8; nt++) {
            mxA = fmaxf(mxA, fmaxf(cs[nt][0], cs[nt][1]));
            mxB = fmaxf(mxB, fmaxf(cs[nt][2], cs[nt][3]));
        }
        mxA = fmaxf(mxA, __shfl_xor_sync(0xffffffffu, mxA, 1));
        mxA = fmaxf(mxA, __shfl_xor_sync(0xffffffffu, mxA, 2));
        mxB = fmaxf(mxB, __shfl_xor_sync(0xffffffffu, mxB, 1));
        mxB = fmaxf(mxB, __shfl_xor_sync(0xffffffffu, mxB, 2));
        float mnA = fmaxf(mA, mxA), mnB = fmaxf(mB, mxB);
        float alA = ex2(mA - mnA), alB = ex2(mB - mnB);

        uint32_t pa[4][4];
        __half2 s2A = __floats2half2_rn(0.f, 0.f), s2B = s2A;
        #pragma unroll
        for (int ks = 0; ks < 4; ks++) {
            #pragma unroll
            for (int half = 0; half < 2; half++) {
                int nt = 2 * ks + half;
                uint32_t eA = ex2h2(pkh(cs[nt][0] - mnA, cs[nt][1] - mnA));
                uint32_t eB = ex2h2(pkh(cs[nt][2] - mnB, cs[nt][3] - mnB));
                pa[ks][2 * half]     = eA;
                pa[ks][2 * half + 1] = eB;
                s2A = __hadd2(s2A, *(__half2*)&eA);
                s2B = __hadd2(s2B, *(__half2*)&eB);
            }
        }
        float psA = __low2float(s2A) + __high2float(s2A);
        float psB = __low2float(s2B) + __high2float(s2B);
        lA = lA * alA + psA; mA = mnA;
        lB = lB * alB + psB; mB = mnB;

        #pragma unroll
        for (int nt = 0; nt < 8; nt++) {
            co[nt][0] *= alA; co[nt][1] *= alA;
            co[nt][2] *= alB; co[nt][3] *= alB;
        }
        #pragma unroll
        for (int ks = 0; ks < 4; ks++) {
            int ko = ks * 16;
            uint32_t vh[8][2];
            #pragma unroll
            for (int dt = 0; dt < 4; dt++) {
                int offv = ((ko + (lid & 15)) * KVP + dt * 16 + ((lid >> 4) & 1) * 8) * 2;
                ldsm4t(vh[2*dt][0], vh[2*dt][1], vh[2*dt+1][0], vh[2*dt+1][1], aV + offv);
            }
            #pragma unroll
            for (int nt = 0; nt < 8; nt++)
                mma_f16(co[nt], pa[ks][0], pa[ks][1], pa[ks][2], pa[ks][3],
                        vh[nt][0], vh[nt][1]);
        }
    }

    lA += __shfl_xor_sync(0xffffffffu, lA, 1);
    lA += __shfl_xor_sync(0xffffffffu, lA, 2);
    lB += __shfl_xor_sync(0xffffffffu, lB, 1);
    lB += __shfl_xor_sync(0xffffffffu, lB, 2);

    float invA = 1.f / lA, invB = 1.f / lB;
    int rA = qt * 128 + wm + (lid >> 2);
    #pragma unroll
    for (int nt = 0; nt < 8; nt++) {
        int col = head * HDq + nt * 8 + (lid & 3) * 2;
        size_t base = (size_t)(b * Nq + rA) * Cq + col;
        *(uint32_t*)&g_att[base] = pkh(co[nt][0] * invA, co[nt][1] * invA);
        size_t base2 = (size_t)(b * Nq + rA + 8) * Cq + col;
        *(uint32_t*)&g_att[base2] = pkh(co[nt][2] * invB, co[nt][3] * invB);
    }
}

extern "C" void kernel_launch(void* const* d_in, const int* in_sizes, int n_in,
                              void* d_out, int out_size) {
    const float* x    = (const float*)d_in[0];
    const float* Wq   = (const float*)d_in[1];
    const float* Wk   = (const float*)d_in[2];
    const float* Wv   = (const float*)d_in[3];
    const float* Wp   = (const float*)d_in[4];
    const float* bp   = (const float*)d_in[5];
    const float* la_q = (const float*)d_in[6];
    const float* lb_q = (const float*)d_in[7];
    const float* la_k = (const float*)d_in[8];
    const float* lb_k = (const float*)d_in[9];
    const float* la_v = (const float*)d_in[10];
    const float* lb_v = (const float*)d_in[11];
    const float* bw   = (const float*)d_in[12];
    float* out = (float*)d_out;

    convert_x_kernel<<<(ROWS * Cq / 4 + 255) / 256, 256>>>(x);
    wprime_kernel<<<dim3(24, 24, 4), 256>>>(Wq, Wk, Wv, Wp,
                                            la_q, lb_q, la_k, lb_k, la_v, lb_v, bw);

    cudaFuncSetAttribute(gemm_qkv_kernel, cudaFuncAttributeMaxDynamicSharedMemorySize, GEMM_DSMEM);
    gemm_qkv_kernel<<<dim3(6, 64, 3), 256, GEMM_DSMEM>>>();

    cudaFuncSetAttribute(attn_kernel, cudaFuncAttributeMaxDynamicSharedMemorySize, ATTN_SMEM);
    attn_kernel<<<dim3(Nq / 128, Hq, Bq), 256, ATTN_SMEM>>>();

    cudaFuncSetAttribute(gemm_out_kernel, cudaFuncAttributeMaxDynamicSharedMemorySize, GEMM_DSMEM);
    gemm_out_kernel<<<dim3(6, 64), 256, GEMM_DSMEM>>>(bp, out);
}